// round 1
// baseline (speedup 1.0000x reference)
#include <cuda_runtime.h>
#include <cstdint>

#define HH   256
#define WW   256
#define BATCH 16
#define HW   65536
#define CIN  12
#define CNOISE 3
#define PERCC 48
#define HID  128
#define TDIM 256
#define TPB  256

// SMEM layout (floats)
#define OFF_W2T 0          // [128][128] k-major
#define OFF_W1T 16384      // [48][128]  k-major
#define OFF_W3T 22528      // [128][12]  k-major
#define OFF_WP  24064      // [48*9]
#define OFF_BP  24496      // [48]
#define OFF_B1  24544      // [128]
#define OFF_B2  24672      // [128]
#define SMEM_FLOATS 24800
#define SMEM_BYTES (SMEM_FLOATS * 4)

// packed fp32x2 helpers (sm_100+ PTX; 2 fused FMAs per instruction)
#define FMA2(d, a, b, c) \
    asm("fma.rn.f32x2 %0, %1, %2, %3;" : "=l"(d) : "l"(a), "l"(b), "l"(c))
#define PACKF(out, lo, hi) \
    asm("mov.b64 %0, {%1, %2};" : "=l"(out) : "f"(lo), "f"(hi))
#define UNPACKF(lo, hi, in) \
    asm("mov.b64 {%0, %1}, %2;" : "=f"(lo), "=f"(hi) : "l"(in))

__device__ float g_emb[BATCH * CNOISE];

// ---------------------------------------------------------------------------
// Time-embedding kernel: emb[b][j] = b_time[j] + sum_k silu(pe[b,k]) w_time[j,k]
// pe = concat(sin(t*invf), cos(t*invf)), invf[f] = 10000^(-2f/256).
// Tiny (48 results); use fp64 transcendentals for robustness against any
// fast-math compile flags (sin.approx is unusable at |ang| ~ 1000 rad).
// ---------------------------------------------------------------------------
__global__ void emb_kernel(const int* __restrict__ t,
                           const float* __restrict__ w_time,
                           const float* __restrict__ b_time) {
    int tid = threadIdx.x;
    if (tid >= BATCH * CNOISE) return;
    int b = tid / CNOISE, j = tid % CNOISE;
    float tb = (float)t[b];
    float acc = b_time[j];
    const double LN1E4 = 9.210340371976184;  // ln(10000)
    for (int k = 0; k < TDIM; k++) {
        int f = (k < TDIM / 2) ? k : (k - TDIM / 2);
        float invf = (float)exp(-LN1E4 * ((double)(2 * f) / 256.0));
        float ang = tb * invf;  // fp32 product, matching reference
        double pe_d = (k < TDIM / 2) ? sin((double)ang) : cos((double)ang);
        float pe = (float)pe_d;
        float s = pe / (1.0f + (float)exp(-(double)pe));  // silu
        acc = fmaf(s, w_time[j * TDIM + k], acc);
    }
    g_emb[tid] = acc;
}

// ---------------------------------------------------------------------------
// Fused main kernel: one thread per pixel.
//   perc[48]  = depthwise 3x3 (group g = o/4, channel g of concat[x, hidden])
//   h1[128]   = relu(W1 perc + b1)
//   h2 chunks = relu(W2 h1 + b2)  -> immediately folded into out12 += W3 h2
//   outputs: hidden_out = out[3:12], noise = out[0:3] + emb[b]
// All GEMM weights transposed to k-major in SMEM so (o,o+1) pairs are
// contiguous for fma.rn.f32x2, loaded via broadcast LDS.128.
// ---------------------------------------------------------------------------
__global__ void __launch_bounds__(TPB, 1)
canet_main(const float* __restrict__ xin, const float* __restrict__ hin,
           const float* __restrict__ wp, const float* __restrict__ bp,
           const float* __restrict__ w1, const float* __restrict__ b1,
           const float* __restrict__ w2, const float* __restrict__ b2,
           const float* __restrict__ w3, float* __restrict__ dout) {
    extern __shared__ float smem[];
    float* s_w2t = smem + OFF_W2T;
    float* s_w1t = smem + OFF_W1T;
    float* s_w3t = smem + OFF_W3T;
    float* s_wp  = smem + OFF_WP;
    float* s_bp  = smem + OFF_BP;
    float* s_b1  = smem + OFF_B1;
    float* s_b2  = smem + OFF_B2;

    // Cooperative weight load + transpose (conflict-free STS; strided LDG is
    // L2-hot after the first wave).
    for (int i = threadIdx.x; i < HID * HID; i += TPB)
        s_w2t[i] = w2[(i % HID) * HID + (i / HID)];
    for (int i = threadIdx.x; i < PERCC * HID; i += TPB)
        s_w1t[i] = w1[(i % HID) * PERCC + (i / HID)];
    for (int i = threadIdx.x; i < HID * CIN; i += TPB)
        s_w3t[i] = w3[(i % CIN) * HID + (i / CIN)];
    for (int i = threadIdx.x; i < PERCC * 9; i += TPB) s_wp[i] = wp[i];
    if (threadIdx.x < PERCC) s_bp[threadIdx.x] = bp[threadIdx.x];
    if (threadIdx.x < HID) {
        s_b1[threadIdx.x] = b1[threadIdx.x];
        s_b2[threadIdx.x] = b2[threadIdx.x];
    }
    __syncthreads();

    int pid = blockIdx.x * TPB + threadIdx.x;
    int b   = pid >> 16;
    int yx  = pid & (HW - 1);
    int y   = yx >> 8;
    int xw  = yx & 255;

    // ---- depthwise perceive conv ----
    float percv[PERCC];
#pragma unroll
    for (int g = 0; g < CIN; g++) {
        const float* src = (g < CNOISE)
            ? (xin + ((size_t)b * CNOISE + g) * HW)
            : (hin + ((size_t)b * (CIN - CNOISE) + (g - CNOISE)) * HW);
        float win[9];
#pragma unroll
        for (int dy = -1; dy <= 1; dy++)
#pragma unroll
            for (int dx = -1; dx <= 1; dx++) {
                int yy = y + dy, xx = xw + dx;
                float v = 0.0f;
                if (yy >= 0 && yy < HH && xx >= 0 && xx < WW)
                    v = __ldg(src + yy * WW + xx);
                win[(dy + 1) * 3 + (dx + 1)] = v;
            }
#pragma unroll
        for (int j = 0; j < 4; j++) {
            int o = g * 4 + j;
            float a = s_bp[o];
#pragma unroll
            for (int q = 0; q < 9; q++) a = fmaf(win[q], s_wp[o * 9 + q], a);
            percv[o] = a;
        }
    }

    // ---- layer 1: h1 = relu(W1 perc + b1), packed f32x2 accumulators ----
    unsigned long long hp[HID / 2];
#pragma unroll
    for (int q = 0; q < HID / 2; q++)
        hp[q] = ((const unsigned long long*)s_b1)[q];
#pragma unroll
    for (int k = 0; k < PERCC; k++) {
        unsigned long long a2;
        PACKF(a2, percv[k], percv[k]);
        const ulonglong2* wr = (const ulonglong2*)(s_w1t + k * HID);
#pragma unroll
        for (int q = 0; q < 32; q++) {
            ulonglong2 wv = wr[q];
            FMA2(hp[2 * q], a2, wv.x, hp[2 * q]);
            FMA2(hp[2 * q + 1], a2, wv.y, hp[2 * q + 1]);
        }
    }
    float h1v[HID];
#pragma unroll
    for (int q = 0; q < HID / 2; q++) {
        float lo, hi;
        UNPACKF(lo, hi, hp[q]);
        h1v[2 * q]     = fmaxf(lo, 0.0f);
        h1v[2 * q + 1] = fmaxf(hi, 0.0f);
    }

    // ---- layer 2 (chunks of 32 out-ch) fused with layer 3 ----
    unsigned long long outp[6];
#pragma unroll
    for (int j = 0; j < 6; j++) outp[j] = 0ull;  // (0.f, 0.f)

#pragma unroll
    for (int ch = 0; ch < 4; ch++) {
        unsigned long long acc[16];
        const unsigned long long* binit =
            (const unsigned long long*)s_b2 + ch * 16;
#pragma unroll
        for (int q = 0; q < 16; q++) acc[q] = binit[q];

#pragma unroll
        for (int k = 0; k < HID; k++) {
            unsigned long long a2;
            PACKF(a2, h1v[k], h1v[k]);
            const ulonglong2* wr =
                (const ulonglong2*)(s_w2t + k * HID + ch * 32);
#pragma unroll
            for (int q = 0; q < 8; q++) {
                ulonglong2 wv = wr[q];
                FMA2(acc[2 * q], a2, wv.x, acc[2 * q]);
                FMA2(acc[2 * q + 1], a2, wv.y, acc[2 * q + 1]);
            }
        }
        // relu(h2 chunk) -> out12 += W3 h2  (w3t row = 12 floats, k-major)
#pragma unroll
        for (int i = 0; i < 16; i++) {
            float lo, hi;
            UNPACKF(lo, hi, acc[i]);
            lo = fmaxf(lo, 0.0f);
            hi = fmaxf(hi, 0.0f);
            int k2 = ch * 32 + 2 * i;
            unsigned long long pa, pb;
            PACKF(pa, lo, lo);
            PACKF(pb, hi, hi);
            const ulonglong2* w3a = (const ulonglong2*)(s_w3t + k2 * CIN);
            const ulonglong2* w3b = (const ulonglong2*)(s_w3t + (k2 + 1) * CIN);
#pragma unroll
            for (int q = 0; q < 3; q++) {
                ulonglong2 wa = w3a[q];
                FMA2(outp[2 * q], pa, wa.x, outp[2 * q]);
                FMA2(outp[2 * q + 1], pa, wa.y, outp[2 * q + 1]);
                ulonglong2 wb = w3b[q];
                FMA2(outp[2 * q], pb, wb.x, outp[2 * q]);
                FMA2(outp[2 * q + 1], pb, wb.y, outp[2 * q + 1]);
            }
        }
    }

    float outv[12];
#pragma unroll
    for (int q = 0; q < 6; q++) UNPACKF(outv[2 * q], outv[2 * q + 1], outp[q]);

    // ---- write outputs: hidden_out (B,9,H,W) then noise_prediction (B,3,H,W)
    float* out_hidden = dout;
    float* out_noise  = dout + (size_t)BATCH * 9 * HW;
#pragma unroll
    for (int c = 0; c < 3; c++)
        out_noise[((size_t)b * 3 + c) * HW + yx] = outv[c] + g_emb[b * 3 + c];
#pragma unroll
    for (int c = 3; c < 12; c++)
        out_hidden[((size_t)b * 9 + (c - 3)) * HW + yx] = outv[c];
}

extern "C" void kernel_launch(void* const* d_in, const int* in_sizes, int n_in,
                              void* d_out, int out_size) {
    const float* x      = (const float*)d_in[0];
    const float* hid    = (const float*)d_in[1];
    const int*   t      = (const int*)d_in[2];
    const float* wp     = (const float*)d_in[3];
    const float* bp     = (const float*)d_in[4];
    const float* w1     = (const float*)d_in[5];
    const float* b1     = (const float*)d_in[6];
    const float* w2     = (const float*)d_in[7];
    const float* b2     = (const float*)d_in[8];
    const float* w3     = (const float*)d_in[9];
    const float* w_time = (const float*)d_in[10];
    const float* b_time = (const float*)d_in[11];
    float* out = (float*)d_out;

    cudaFuncSetAttribute(canet_main,
                         cudaFuncAttributeMaxDynamicSharedMemorySize,
                         SMEM_BYTES);

    emb_kernel<<<1, 64>>>(t, w_time, b_time);
    canet_main<<<(BATCH * HW) / TPB, TPB, SMEM_BYTES>>>(
        x, hid, wp, bp, w1, b1, w2, b2, w3, out);
}

// round 2
// speedup vs baseline: 1.4588x; 1.4588x over previous
#include <cuda_runtime.h>
#include <cstdint>

#define HH   256
#define WW   256
#define BATCH 16
#define HW   65536
#define CIN  12
#define CNOISE 3
#define PERCC 48
#define HID  128
#define TDIM 256
#define TPB  256
#define TP   128                       // pixels per tile (half a row)
#define NTILES (BATCH * HW / TP)       // 8192

// SMEM layout (float offsets)
#define OFF_W2T 0                      // [128][128] k-major
#define OFF_W1T 16384                  // [48][128]  k-major
#define OFF_W3T 22528                  // [128][12]  k-major
#define OFF_WP  24064                  // [48*9]
#define OFF_BP  24496                  // [48]
#define OFF_B1  24544                  // [128]
#define OFF_B2  24672                  // [128]
#define OFF_R1  24800                  // h1s  [128][128]
#define OFF_R2  41184                  // percs[48][128] / h2s [128][128] (overlaid)
#define SMEM_FLOATS 57568
#define SMEM_BYTES (SMEM_FLOATS * 4)   // 230272 <= 232448 max dyn smem

typedef unsigned long long ull;

#define FMA2(d, a, b) \
    asm("fma.rn.f32x2 %0, %1, %2, %0;" : "+l"(d) : "l"(a), "l"(b))
#define PACKF(out, lo, hi) \
    asm("mov.b64 %0, {%1, %2};" : "=l"(out) : "f"(lo), "f"(hi))
#define UNPACKF(lo, hi, in) \
    asm("mov.b64 {%0, %1}, %2;" : "=f"(lo), "=f"(hi) : "l"(in))

__device__ float g_emb[BATCH * CNOISE];

// ---------------------------------------------------------------------------
// Time embedding (tiny; fp64 transcendentals for large-angle sin/cos safety)
// ---------------------------------------------------------------------------
__global__ void emb_kernel(const int* __restrict__ t,
                           const float* __restrict__ w_time,
                           const float* __restrict__ b_time) {
    int tid = threadIdx.x;
    if (tid >= BATCH * CNOISE) return;
    int b = tid / CNOISE, j = tid % CNOISE;
    float tb = (float)t[b];
    float acc = b_time[j];
    const double LN1E4 = 9.210340371976184;
    for (int k = 0; k < TDIM; k++) {
        int f = (k < TDIM / 2) ? k : (k - TDIM / 2);
        float invf = (float)exp(-LN1E4 * ((double)(2 * f) / 256.0));
        float ang = tb * invf;
        float pe = (float)((k < TDIM / 2) ? sin((double)ang) : cos((double)ang));
        float s = pe / (1.0f + (float)exp(-(double)pe));
        acc = fmaf(s, w_time[j * TDIM + k], acc);
    }
    g_emb[tid] = acc;
}

// ---------------------------------------------------------------------------
// Persistent fused kernel. Per 128-pixel tile:
//   A1: depthwise 3x3 -> percs[48][128]   (region2)
//   A2: relu(W1 . + b1) -> h1s[128][128]  (region1)   8ch x 8px register tiles
//   B : relu(W2 . + b2) -> h2s[128][128]  (region2)   8ch x 8px register tiles
//   C : W3 . + emb -> global               6ch x 1px per thread
// ---------------------------------------------------------------------------
__global__ void __launch_bounds__(TPB, 1)
canet_main(const float* __restrict__ xin, const float* __restrict__ hin,
           const float* __restrict__ wp, const float* __restrict__ bp,
           const float* __restrict__ w1, const float* __restrict__ b1,
           const float* __restrict__ w2, const float* __restrict__ b2,
           const float* __restrict__ w3, float* __restrict__ dout) {
    extern __shared__ float sm[];
    float* s_w2t = sm + OFF_W2T;
    float* s_w1t = sm + OFF_W1T;
    float* s_w3t = sm + OFF_W3T;
    float* s_wp  = sm + OFF_WP;
    float* s_bp  = sm + OFF_BP;
    float* s_b1  = sm + OFF_B1;
    float* s_b2  = sm + OFF_B2;
    float* s_h1  = sm + OFF_R1;
    float* s_pc  = sm + OFF_R2;   // percs
    float* s_h2  = sm + OFF_R2;   // h2 (overlaid; percs dead by then)

    const int tx = threadIdx.x;

    // One-time weight load (coalesced LDG; STS conflicts amortized per-CTA)
    for (int i = tx; i < HID * HID; i += TPB)
        s_w2t[(i % HID) * HID + (i / HID)] = w2[i];
    for (int i = tx; i < HID * PERCC; i += TPB)
        s_w1t[(i % PERCC) * HID + (i / PERCC)] = w1[i];
    for (int i = tx; i < CIN * HID; i += TPB)
        s_w3t[(i % HID) * CIN + (i / HID)] = w3[i];
    for (int i = tx; i < PERCC * 9; i += TPB) s_wp[i] = wp[i];
    if (tx < PERCC) s_bp[tx] = bp[tx];
    if (tx < HID) { s_b1[tx] = b1[tx]; s_b2[tx] = b2[tx]; }
    __syncthreads();

    const int pxg = tx & 15, chg = tx >> 4;
    const int pb = pxg * 8, cb = chg * 8;

    for (int tile = blockIdx.x; tile < NTILES; tile += gridDim.x) {
        const int b   = tile >> 9;
        const int rem = tile & 511;
        const int y   = rem >> 1;
        const int x0  = (rem & 1) << 7;

        // ---- A1: depthwise conv -> percs[g*4+j][px] ----
#pragma unroll
        for (int i = 0; i < 6; i++) {
            int tt = tx + TPB * i;
            int px = tt & 127;
            int g  = tt >> 7;
            const float* src = (g < CNOISE)
                ? (xin + ((size_t)b * CNOISE + g) * HW)
                : (hin + ((size_t)b * (CIN - CNOISE) + (g - CNOISE)) * HW);
            int xg = x0 + px;
            float win[9];
#pragma unroll
            for (int dy = -1; dy <= 1; dy++)
#pragma unroll
                for (int dx = -1; dx <= 1; dx++) {
                    int yy = y + dy, xx = xg + dx;
                    float v = 0.0f;
                    if (yy >= 0 && yy < HH && xx >= 0 && xx < WW)
                        v = __ldg(src + yy * WW + xx);
                    win[(dy + 1) * 3 + (dx + 1)] = v;
                }
#pragma unroll
            for (int j = 0; j < 4; j++) {
                int o = g * 4 + j;
                float a = s_bp[o];
#pragma unroll
                for (int q = 0; q < 9; q++) a = fmaf(win[q], s_wp[o * 9 + q], a);
                s_pc[o * TP + px] = a;
            }
        }
        __syncthreads();

        // ---- A2: layer1, 8ch x 8px per thread, K=48 ----
        {
            ull acc[32];
#pragma unroll
            for (int c = 0; c < 8; c++) {
                float bv = s_b1[cb + c];
                ull d; PACKF(d, bv, bv);
                acc[c * 4] = d; acc[c * 4 + 1] = d;
                acc[c * 4 + 2] = d; acc[c * 4 + 3] = d;
            }
#pragma unroll 8
            for (int k = 0; k < PERCC; k++) {
                ulonglong2 a01 = *(const ulonglong2*)(s_pc + k * TP + pb);
                ulonglong2 a23 = *(const ulonglong2*)(s_pc + k * TP + pb + 4);
                float4 wv0 = *(const float4*)(s_w1t + k * HID + cb);
                float4 wv1 = *(const float4*)(s_w1t + k * HID + cb + 4);
                ull wd[8];
                PACKF(wd[0], wv0.x, wv0.x); PACKF(wd[1], wv0.y, wv0.y);
                PACKF(wd[2], wv0.z, wv0.z); PACKF(wd[3], wv0.w, wv0.w);
                PACKF(wd[4], wv1.x, wv1.x); PACKF(wd[5], wv1.y, wv1.y);
                PACKF(wd[6], wv1.z, wv1.z); PACKF(wd[7], wv1.w, wv1.w);
#pragma unroll
                for (int c = 0; c < 8; c++) {
                    FMA2(acc[c * 4 + 0], a01.x, wd[c]);
                    FMA2(acc[c * 4 + 1], a01.y, wd[c]);
                    FMA2(acc[c * 4 + 2], a23.x, wd[c]);
                    FMA2(acc[c * 4 + 3], a23.y, wd[c]);
                }
            }
            __syncthreads();   // percs fully consumed before h1 writes? no:
                               // h1 (region1) doesn't alias percs; this sync is
                               // not required for A2 writes, but keeps phases
                               // clean and is needed before B reads h1 anyway.
#pragma unroll
            for (int c = 0; c < 8; c++)
#pragma unroll
                for (int pp = 0; pp < 4; pp++) {
                    float lo, hi; UNPACKF(lo, hi, acc[c * 4 + pp]);
                    lo = fmaxf(lo, 0.0f); hi = fmaxf(hi, 0.0f);
                    ull r; PACKF(r, lo, hi);
                    *(ull*)(s_h1 + (cb + c) * TP + pb + pp * 2) = r;
                }
        }
        __syncthreads();

        // ---- B: layer2, 8ch x 8px per thread, K=128 (h2 overlays percs) ----
        {
            ull acc[32];
#pragma unroll
            for (int c = 0; c < 8; c++) {
                float bv = s_b2[cb + c];
                ull d; PACKF(d, bv, bv);
                acc[c * 4] = d; acc[c * 4 + 1] = d;
                acc[c * 4 + 2] = d; acc[c * 4 + 3] = d;
            }
#pragma unroll 8
            for (int k = 0; k < HID; k++) {
                ulonglong2 a01 = *(const ulonglong2*)(s_h1 + k * TP + pb);
                ulonglong2 a23 = *(const ulonglong2*)(s_h1 + k * TP + pb + 4);
                float4 wv0 = *(const float4*)(s_w2t + k * HID + cb);
                float4 wv1 = *(const float4*)(s_w2t + k * HID + cb + 4);
                ull wd[8];
                PACKF(wd[0], wv0.x, wv0.x); PACKF(wd[1], wv0.y, wv0.y);
                PACKF(wd[2], wv0.z, wv0.z); PACKF(wd[3], wv0.w, wv0.w);
                PACKF(wd[4], wv1.x, wv1.x); PACKF(wd[5], wv1.y, wv1.y);
                PACKF(wd[6], wv1.z, wv1.z); PACKF(wd[7], wv1.w, wv1.w);
#pragma unroll
                for (int c = 0; c < 8; c++) {
                    FMA2(acc[c * 4 + 0], a01.x, wd[c]);
                    FMA2(acc[c * 4 + 1], a01.y, wd[c]);
                    FMA2(acc[c * 4 + 2], a23.x, wd[c]);
                    FMA2(acc[c * 4 + 3], a23.y, wd[c]);
                }
            }
            __syncthreads();   // all reads of h1/percs done before h2 overwrite
#pragma unroll
            for (int c = 0; c < 8; c++)
#pragma unroll
                for (int pp = 0; pp < 4; pp++) {
                    float lo, hi; UNPACKF(lo, hi, acc[c * 4 + pp]);
                    lo = fmaxf(lo, 0.0f); hi = fmaxf(hi, 0.0f);
                    ull r; PACKF(r, lo, hi);
                    *(ull*)(s_h2 + (cb + c) * TP + pb + pp * 2) = r;
                }
        }
        __syncthreads();

        // ---- C: layer3 + emb + global store ----
        {
            int px  = tx & 127;
            int grp = tx >> 7;          // 0: ch 0..5, 1: ch 6..11
            int c0  = grp * 6;
            ull a3_0 = 0, a3_1 = 0, a3_2 = 0;
#pragma unroll 8
            for (int k = 0; k < HID; k++) {
                float av = s_h2[k * TP + px];
                ull a2; PACKF(a2, av, av);
                const ull* wr = (const ull*)(s_w3t + k * CIN + c0);
                FMA2(a3_0, a2, wr[0]);
                FMA2(a3_1, a2, wr[1]);
                FMA2(a3_2, a2, wr[2]);
            }
            float ov[6];
            UNPACKF(ov[0], ov[1], a3_0);
            UNPACKF(ov[2], ov[3], a3_1);
            UNPACKF(ov[4], ov[5], a3_2);

            size_t yx = (size_t)y * WW + x0 + px;
            float* out_hidden = dout;
            float* out_noise  = dout + (size_t)BATCH * 9 * HW;
#pragma unroll
            for (int j = 0; j < 6; j++) {
                int c = c0 + j;
                if (c < CNOISE)
                    out_noise[((size_t)b * 3 + c) * HW + yx] =
                        ov[j] + g_emb[b * 3 + c];
                else
                    out_hidden[((size_t)b * 9 + (c - 3)) * HW + yx] = ov[j];
            }
        }
        __syncthreads();   // h2 consumed before next tile's percs overwrite
    }
}

extern "C" void kernel_launch(void* const* d_in, const int* in_sizes, int n_in,
                              void* d_out, int out_size) {
    const float* x      = (const float*)d_in[0];
    const float* hid    = (const float*)d_in[1];
    const int*   t      = (const int*)d_in[2];
    const float* wp     = (const float*)d_in[3];
    const float* bp     = (const float*)d_in[4];
    const float* w1     = (const float*)d_in[5];
    const float* b1     = (const float*)d_in[6];
    const float* w2     = (const float*)d_in[7];
    const float* b2     = (const float*)d_in[8];
    const float* w3     = (const float*)d_in[9];
    const float* w_time = (const float*)d_in[10];
    const float* b_time = (const float*)d_in[11];
    float* out = (float*)d_out;

    cudaFuncSetAttribute(canet_main,
                         cudaFuncAttributeMaxDynamicSharedMemorySize,
                         SMEM_BYTES);

    int nsm = 148;
    if (cudaDeviceGetAttribute(&nsm, cudaDevAttrMultiProcessorCount, 0)
        != cudaSuccess || nsm <= 0)
        nsm = 148;

    emb_kernel<<<1, 64>>>(t, w_time, b_time);
    canet_main<<<nsm, TPB, SMEM_BYTES>>>(
        x, hid, wp, bp, w1, b1, w2, b2, w3, out);
}

// round 4
// speedup vs baseline: 5.1933x; 3.5600x over previous
#include <cuda_runtime.h>
#include <cstdint>

#define HH 256
#define WW 256
#define BATCH 16
#define HW 65536
#define CIN 12
#define CNOISE 3
#define PERCC 48
#define HID 128
#define TDIM 256
#define TPB 256
#define TP 128
#define NTILES (BATCH * HW / TP)   // 8192

// SMEM layout (float indices)
#define OW2  0          // W2 [128][128] swizzled tf32
#define OW1  16384      // W1 [128][52]  tf32 (pad 52, conflict-free)
#define OW3  23040      // W3 [12][128]  swizzled tf32 (rows 12-15 read junk)
#define OWP  24576      // wp  48*9 fp32
#define OBP  25008      // bp  48
#define OB1  25056      // b1  128
#define OB2  25184      // b2  128
#define OH1  25312      // h1  [128px][128ch] swizzled tf32
#define OPH2 41696      // perc [128px][52] tf32  /  h2 [128px][128] swizzled
#define SMEM_FLOATS 58080
#define SMEM_BYTES (SMEM_FLOATS * 4)   // 232320

static __device__ __forceinline__ uint32_t f2tf(float f) {
    uint32_t u;
    asm("cvt.rna.tf32.f32 %0, %1;" : "=r"(u) : "f"(f));
    return u;
}

static __device__ __forceinline__ void mma8(float d[4], const uint32_t a[4],
                                            const uint32_t b0, const uint32_t b1) {
    asm volatile(
        "mma.sync.aligned.m16n8k8.row.col.f32.tf32.tf32.f32 "
        "{%0,%1,%2,%3}, {%4,%5,%6,%7}, {%8,%9}, {%0,%1,%2,%3};"
        : "+f"(d[0]), "+f"(d[1]), "+f"(d[2]), "+f"(d[3])
        : "r"(a[0]), "r"(a[1]), "r"(a[2]), "r"(a[3]), "r"(b0), "r"(b1));
}

__device__ float g_emb[BATCH * CNOISE];

// ---------------------------------------------------------------------------
__global__ void emb_kernel(const int* __restrict__ t,
                           const float* __restrict__ w_time,
                           const float* __restrict__ b_time) {
    __shared__ float ss[TDIM];
    int b = blockIdx.x, k = threadIdx.x;
    float tb = (float)t[b];
    int f = (k < TDIM / 2) ? k : (k - TDIM / 2);
    const double LN1E4 = 9.210340371976184;
    float invf = (float)exp(-LN1E4 * ((double)(2 * f) / 256.0));
    float ang = tb * invf;
    float pe = (float)((k < TDIM / 2) ? sin((double)ang) : cos((double)ang));
    ss[k] = pe / (1.0f + (float)exp(-(double)pe));
    __syncthreads();
    if (k < CNOISE) {
        float acc = b_time[k];
        for (int q = 0; q < TDIM; q++)
            acc = fmaf(ss[q], w_time[k * TDIM + q], acc);
        g_emb[b * CNOISE + k] = acc;
    }
}

// ---------------------------------------------------------------------------
// Persistent tile pipeline, tf32 mma.sync GEMMs.
//   conv -> perc[px][52]; L1 mma (K=48) -> relu -> h1[px][128]sw;
//   L2 mma (K=128) -> relu -> h2[px][128]sw (overlays perc);
//   L3 mma (K=128, 12ch) -> +emb -> STG.
// ---------------------------------------------------------------------------
__global__ void __launch_bounds__(TPB, 1)
canet_main(const float* __restrict__ xin, const float* __restrict__ hin,
           const float* __restrict__ wp, const float* __restrict__ bp,
           const float* __restrict__ w1, const float* __restrict__ b1,
           const float* __restrict__ w2, const float* __restrict__ b2,
           const float* __restrict__ w3, float* __restrict__ dout) {
    extern __shared__ float sm[];
    uint32_t* smU = (uint32_t*)sm;
    const int tx = threadIdx.x;

    // ---- one-time weight staging (tf32-rounded, swizzled) ----
    for (int i = tx; i < HID * HID; i += TPB) {
        int o = i >> 7, k = i & 127;
        smU[OW2 + o * 128 + (k ^ ((o & 7) << 2))] = f2tf(w2[i]);
    }
    for (int i = tx; i < HID * PERCC; i += TPB) {
        int o = i / PERCC, k = i % PERCC;
        smU[OW1 + o * 52 + k] = f2tf(w1[i]);
    }
    for (int i = tx; i < CIN * HID; i += TPB) {
        int o = i >> 7, k = i & 127;
        smU[OW3 + o * 128 + (k ^ ((o & 7) << 2))] = f2tf(w3[i]);
    }
    for (int i = tx; i < PERCC * 9; i += TPB) sm[OWP + i] = wp[i];
    if (tx < PERCC) sm[OBP + tx] = bp[tx];
    if (tx < HID) { sm[OB1 + tx] = b1[tx]; sm[OB2 + tx] = b2[tx]; }
    __syncthreads();

    const int w    = tx >> 5, lane = tx & 31;
    const int grp  = lane >> 2, t4 = lane & 3;
    const int cb   = (w & 3) * 32;       // L1/L2 channel base
    const int pxb  = (w >> 2) * 64;      // L1/L2 pixel base
    const int pxb3 = w * 16;             // L3 pixel base
    const int asw  = grp << 2;           // XOR swizzle for frag loads

    float b1v[2][2], b2v[2][2];
#pragma unroll
    for (int i = 0; i < 2; i++)
#pragma unroll
        for (int h = 0; h < 2; h++) {
            b1v[i][h] = sm[OB1 + cb + 16 * i + 8 * h + grp];
            b2v[i][h] = sm[OB2 + cb + 16 * i + 8 * h + grp];
        }

    const int cpx  = tx & 127;           // conv: this thread's pixel
    const int chalf = tx >> 7;           // conv: groups [6h, 6h+6)

    for (int tile = blockIdx.x; tile < NTILES; tile += gridDim.x) {
        const int b   = tile >> 9;
        const int rem = tile & 511;
        const int y   = rem >> 1;
        const int x0  = (rem & 1) << 7;

        // ---- conv: 6 groups (24 ch) per thread -> perc[px][52] tf32 ----
        {
            int xg = x0 + cpx;
#pragma unroll
            for (int gi = 0; gi < 6; gi++) {
                int g = chalf * 6 + gi;
                const float* src = (g < CNOISE)
                    ? (xin + ((size_t)b * CNOISE + g) * HW)
                    : (hin + ((size_t)b * (CIN - CNOISE) + (g - CNOISE)) * HW);
                float win[9];
#pragma unroll
                for (int dy = -1; dy <= 1; dy++)
#pragma unroll
                    for (int dx = -1; dx <= 1; dx++) {
                        int yy = y + dy, xx = xg + dx;
                        float v = 0.0f;
                        if (yy >= 0 && yy < HH && xx >= 0 && xx < WW)
                            v = __ldg(src + yy * WW + xx);
                        win[(dy + 1) * 3 + (dx + 1)] = v;
                    }
                uint4 pk;
                uint32_t* p = (uint32_t*)&pk;
#pragma unroll
                for (int j = 0; j < 4; j++) {
                    int o = g * 4 + j;
                    float a = sm[OBP + o];
#pragma unroll
                    for (int q = 0; q < 9; q++)
                        a = fmaf(win[q], sm[OWP + o * 9 + q], a);
                    p[j] = f2tf(a);
                }
                *(uint4*)(smU + OPH2 + cpx * 52 + g * 4) = pk;
            }
        }
        __syncthreads();

        // ---- L1: 128ch x 128px, K=48 ----
        {
            float acc[2][8][4];
#pragma unroll
            for (int i = 0; i < 2; i++)
#pragma unroll
                for (int j = 0; j < 8; j++)
#pragma unroll
                    for (int q = 0; q < 4; q++) acc[i][j][q] = 0.0f;

#pragma unroll
            for (int s = 0; s < 6; s++) {
                int k0 = 8 * s;
                uint32_t a[2][4];
#pragma unroll
                for (int i = 0; i < 2; i++) {
                    int r = OW1 + (cb + 16 * i + grp) * 52 + k0 + t4;
                    a[i][0] = smU[r];
                    a[i][1] = smU[r + 8 * 52];
                    a[i][2] = smU[r + 4];
                    a[i][3] = smU[r + 8 * 52 + 4];
                }
                uint32_t bf[8][2];
#pragma unroll
                for (int j = 0; j < 8; j++) {
                    int r = OPH2 + (pxb + 8 * j + grp) * 52 + k0 + t4;
                    bf[j][0] = smU[r];
                    bf[j][1] = smU[r + 4];
                }
#pragma unroll
                for (int i = 0; i < 2; i++)
#pragma unroll
                    for (int j = 0; j < 8; j++)
                        mma8(acc[i][j], a[i], bf[j][0], bf[j][1]);
            }
            // relu + bias -> h1 (swizzled)
#pragma unroll
            for (int i = 0; i < 2; i++)
#pragma unroll
                for (int j = 0; j < 8; j++) {
                    int ch0 = cb + 16 * i + grp;
                    int px0 = pxb + 8 * j + 2 * t4;
                    int sw0 = (2 * t4) << 2, sw1 = (2 * t4 + 1) << 2;
                    smU[OH1 + px0 * 128 + (ch0 ^ sw0)] =
                        f2tf(fmaxf(acc[i][j][0] + b1v[i][0], 0.0f));
                    smU[OH1 + (px0 + 1) * 128 + (ch0 ^ sw1)] =
                        f2tf(fmaxf(acc[i][j][1] + b1v[i][0], 0.0f));
                    smU[OH1 + px0 * 128 + ((ch0 + 8) ^ sw0)] =
                        f2tf(fmaxf(acc[i][j][2] + b1v[i][1], 0.0f));
                    smU[OH1 + (px0 + 1) * 128 + ((ch0 + 8) ^ sw1)] =
                        f2tf(fmaxf(acc[i][j][3] + b1v[i][1], 0.0f));
                }
        }
        __syncthreads();

        // ---- L2: 128ch x 128px, K=128 ----
        {
            float acc[2][8][4];
#pragma unroll
            for (int i = 0; i < 2; i++)
#pragma unroll
                for (int j = 0; j < 8; j++)
#pragma unroll
                    for (int q = 0; q < 4; q++) acc[i][j][q] = 0.0f;

#pragma unroll 4
            for (int s = 0; s < 16; s++) {
                int k0 = 8 * s;
                int ka  = (k0 + t4) ^ asw;
                int ka4 = (k0 + t4 + 4) ^ asw;
                uint32_t a[2][4];
#pragma unroll
                for (int i = 0; i < 2; i++) {
                    int r = OW2 + (cb + 16 * i + grp) * 128;
                    a[i][0] = smU[r + ka];
                    a[i][1] = smU[r + 8 * 128 + ka];
                    a[i][2] = smU[r + ka4];
                    a[i][3] = smU[r + 8 * 128 + ka4];
                }
                uint32_t bf[8][2];
#pragma unroll
                for (int j = 0; j < 8; j++) {
                    int r = OH1 + (pxb + 8 * j + grp) * 128;
                    bf[j][0] = smU[r + ka];
                    bf[j][1] = smU[r + ka4];
                }
#pragma unroll
                for (int i = 0; i < 2; i++)
#pragma unroll
                    for (int j = 0; j < 8; j++)
                        mma8(acc[i][j], a[i], bf[j][0], bf[j][1]);
            }
            // relu + bias -> h2 (overlays perc, swizzled)
#pragma unroll
            for (int i = 0; i < 2; i++)
#pragma unroll
                for (int j = 0; j < 8; j++) {
                    int ch0 = cb + 16 * i + grp;
                    int px0 = pxb + 8 * j + 2 * t4;
                    int sw0 = (2 * t4) << 2, sw1 = (2 * t4 + 1) << 2;
                    smU[OPH2 + px0 * 128 + (ch0 ^ sw0)] =
                        f2tf(fmaxf(acc[i][j][0] + b2v[i][0], 0.0f));
                    smU[OPH2 + (px0 + 1) * 128 + (ch0 ^ sw1)] =
                        f2tf(fmaxf(acc[i][j][1] + b2v[i][0], 0.0f));
                    smU[OPH2 + px0 * 128 + ((ch0 + 8) ^ sw0)] =
                        f2tf(fmaxf(acc[i][j][2] + b2v[i][1], 0.0f));
                    smU[OPH2 + (px0 + 1) * 128 + ((ch0 + 8) ^ sw1)] =
                        f2tf(fmaxf(acc[i][j][3] + b2v[i][1], 0.0f));
                }
        }
        __syncthreads();

        // ---- L3: 12ch x 16px per warp, K=128; epilogue ----
        {
            float acc[2][4];
#pragma unroll
            for (int j = 0; j < 2; j++)
#pragma unroll
                for (int q = 0; q < 4; q++) acc[j][q] = 0.0f;

#pragma unroll 4
            for (int s = 0; s < 16; s++) {
                int k0 = 8 * s;
                int ka  = (k0 + t4) ^ asw;
                int ka4 = (k0 + t4 + 4) ^ asw;
                uint32_t a[4];
                a[0] = smU[OW3 + grp * 128 + ka];
                a[1] = smU[OW3 + (grp + 8) * 128 + ka];   // rows 12-15: junk, unused
                a[2] = smU[OW3 + grp * 128 + ka4];
                a[3] = smU[OW3 + (grp + 8) * 128 + ka4];
                uint32_t bf[2][2];
#pragma unroll
                for (int j = 0; j < 2; j++) {
                    int r = OPH2 + (pxb3 + 8 * j + grp) * 128;
                    bf[j][0] = smU[r + ka];
                    bf[j][1] = smU[r + ka4];
                }
#pragma unroll
                for (int j = 0; j < 2; j++)
                    mma8(acc[j], a, bf[j][0], bf[j][1]);
            }

            float* out_noise = dout + (size_t)BATCH * 9 * HW;
            float embv = (grp < CNOISE) ? __ldg(&g_emb[b * 3 + grp]) : 0.0f;
#pragma unroll
            for (int j = 0; j < 2; j++) {
                int px0 = pxb3 + 8 * j + 2 * t4;
                size_t yx = (size_t)y * WW + x0 + px0;
                // c0,c1: ch = grp
                if (grp < CNOISE) {
                    float2 v = make_float2(acc[j][0] + embv, acc[j][1] + embv);
                    *(float2*)(out_noise + ((size_t)b * 3 + grp) * HW + yx) = v;
                } else {
                    float2 v = make_float2(acc[j][0], acc[j][1]);
                    *(float2*)(dout + ((size_t)b * 9 + (grp - 3)) * HW + yx) = v;
                }
                // c2,c3: ch = grp + 8 (valid while < 12)
                if (grp < 4) {
                    float2 v = make_float2(acc[j][2], acc[j][3]);
                    *(float2*)(dout + ((size_t)b * 9 + (grp + 5)) * HW + yx) = v;
                }
            }
        }
        __syncthreads();   // protect h2 region before next tile's conv
    }
}

extern "C" void kernel_launch(void* const* d_in, const int* in_sizes, int n_in,
                              void* d_out, int out_size) {
    const float* x      = (const float*)d_in[0];
    const float* hid    = (const float*)d_in[1];
    const int*   t      = (const int*)d_in[2];
    const float* wp     = (const float*)d_in[3];
    const float* bp     = (const float*)d_in[4];
    const float* w1     = (const float*)d_in[5];
    const float* b1     = (const float*)d_in[6];
    const float* w2     = (const float*)d_in[7];
    const float* b2     = (const float*)d_in[8];
    const float* w3     = (const float*)d_in[9];
    const float* w_time = (const float*)d_in[10];
    const float* b_time = (const float*)d_in[11];
    float* out = (float*)d_out;

    cudaFuncSetAttribute(canet_main,
                         cudaFuncAttributeMaxDynamicSharedMemorySize,
                         SMEM_BYTES);

    int nsm = 148;
    if (cudaDeviceGetAttribute(&nsm, cudaDevAttrMultiProcessorCount, 0)
        != cudaSuccess || nsm <= 0)
        nsm = 148;

    emb_kernel<<<BATCH, TDIM>>>(t, w_time, b_time);
    canet_main<<<nsm, TPB, SMEM_BYTES>>>(
        x, hid, wp, bp, w1, b1, w2, b2, w3, out);
}

// round 5
// speedup vs baseline: 7.4233x; 1.4294x over previous
#include <cuda_runtime.h>
#include <cuda_fp16.h>
#include <cstdint>

#define HH 256
#define WW 256
#define BATCH 16
#define HW 65536
#define CIN 12
#define CNOISE 3
#define PERCC 48
#define HID 128
#define TDIM 256
#define TPB 512
#define TP 128
#define NTILES (BATCH * HW / TP)   // 8192

// SMEM word (b32) offsets; fp16 data stored as packed pairs (1 word = 2 ch)
#define OW2  0          // W2 [128 rows][64 words] swizzled
#define OW1  8192       // W1 [128 rows][32 words] (24 real) swizzled
#define OW3  12288      // W3 [16 rows][64 words] swizzled (rows 12-15 zero)
#define OWP  13312      // wp 48*9 fp32
#define OBP  13744      // bp 48 fp32
#define OB1  13792      // b1 128 fp32
#define OB2  13920      // b2 128 fp32
#define OH1  14048      // h1 [128 px][64 words] swizzled
#define OPH2 22240      // perc [128 px][32 words] / h2 [128 px][64 words]
#define SMEM_WORDS 30432
#define SMEM_BYTES (SMEM_WORDS * 4)   // 121728

static __device__ __forceinline__ uint32_t packh2(float lo, float hi) {
    __half2 h = __floats2half2_rn(lo, hi);
    return *(uint32_t*)&h;
}

static __device__ __forceinline__ void mma16(float d[4], const uint32_t a[4],
                                             uint32_t b0, uint32_t b1) {
    asm volatile(
        "mma.sync.aligned.m16n8k16.row.col.f32.f16.f16.f32 "
        "{%0,%1,%2,%3}, {%4,%5,%6,%7}, {%8,%9}, {%0,%1,%2,%3};"
        : "+f"(d[0]), "+f"(d[1]), "+f"(d[2]), "+f"(d[3])
        : "r"(a[0]), "r"(a[1]), "r"(a[2]), "r"(a[3]), "r"(b0), "r"(b1));
}

__device__ float g_emb[BATCH * CNOISE];

// ---------------------------------------------------------------------------
__global__ void emb_kernel(const int* __restrict__ t,
                           const float* __restrict__ w_time,
                           const float* __restrict__ b_time) {
    __shared__ float ss[TDIM];
    int b = blockIdx.x, k = threadIdx.x;
    float tb = (float)t[b];
    int f = (k < TDIM / 2) ? k : (k - TDIM / 2);
    const double LN1E4 = 9.210340371976184;
    float invf = (float)exp(-LN1E4 * ((double)(2 * f) / 256.0));
    float ang = tb * invf;
    float pe = (float)((k < TDIM / 2) ? sin((double)ang) : cos((double)ang));
    ss[k] = pe / (1.0f + (float)exp(-(double)pe));
    __syncthreads();
    if (k < CNOISE) {
        float acc = b_time[k];
        for (int q = 0; q < TDIM; q++)
            acc = fmaf(ss[q], w_time[k * TDIM + q], acc);
        g_emb[b * CNOISE + k] = acc;
    }
}

// ---------------------------------------------------------------------------
// Persistent pipeline, fp16 m16n8k16 MMAs, 16 warps.
// Warp tile L1/L2: 16ch x 64px (1 m-frag x 8 n-frags).
// relu outputs packed to fp16 ch-pairs via shfl.xor(4) lane exchange.
// ---------------------------------------------------------------------------
__global__ void __launch_bounds__(TPB, 1)
canet_main(const float* __restrict__ xin, const float* __restrict__ hin,
           const float* __restrict__ wp, const float* __restrict__ bp,
           const float* __restrict__ w1, const float* __restrict__ b1,
           const float* __restrict__ w2, const float* __restrict__ b2,
           const float* __restrict__ w3, float* __restrict__ dout) {
    extern __shared__ float sm[];
    uint32_t* smU = (uint32_t*)sm;
    const int tx = threadIdx.x;

    // ---- one-time staging ----
    for (int i = tx; i < 1024; i += TPB) smU[OW3 + i] = 0u;   // zero W3 (junk rows)
    __syncthreads();
    for (int i = tx; i < HID * 64; i += TPB) {
        int o = i >> 6, kw = i & 63;
        smU[OW2 + o * 64 + (kw ^ ((o & 7) << 2))] =
            packh2(w2[o * HID + 2 * kw], w2[o * HID + 2 * kw + 1]);
    }
    for (int i = tx; i < HID * 24; i += TPB) {
        int o = i / 24, kw = i % 24;
        smU[OW1 + o * 32 + (kw ^ ((o & 7) << 2))] =
            packh2(w1[o * PERCC + 2 * kw], w1[o * PERCC + 2 * kw + 1]);
    }
    for (int i = tx; i < CIN * 64; i += TPB) {
        int o = i >> 6, kw = i & 63;
        smU[OW3 + o * 64 + (kw ^ ((o & 7) << 2))] =
            packh2(w3[o * HID + 2 * kw], w3[o * HID + 2 * kw + 1]);
    }
    for (int i = tx; i < PERCC * 9; i += TPB) sm[OWP + i] = wp[i];
    if (tx < PERCC) sm[OBP + tx] = bp[tx];
    if (tx < HID) { sm[OB1 + tx] = b1[tx]; sm[OB2 + tx] = b2[tx]; }
    __syncthreads();

    const int w    = tx >> 5, lane = tx & 31;
    const int grp  = lane >> 2, t4 = lane & 3;
    const int asw  = grp << 2;
    const int cb   = (w & 7) * 16;       // L1/L2 channel base (16 ch per warp)
    const int pxb  = (w >> 3) * 64;      // L1/L2 pixel base
    const int pxb3 = w * 8;              // L3 pixel base

    const float b1v0 = sm[OB1 + cb + grp],     b1v1 = sm[OB1 + cb + 8 + grp];
    const float b2v0 = sm[OB2 + cb + grp],     b2v1 = sm[OB2 + cb + 8 + grp];

    const int cpx   = tx & 127;          // conv pixel
    const int cquad = tx >> 7;           // conv groups [3q, 3q+3)
    const int widxL = (cb >> 1) + (grp >> 1);   // store word base (both layers)

    for (int tile = blockIdx.x; tile < NTILES; tile += gridDim.x) {
        const int b   = tile >> 9;
        const int rem = tile & 511;
        const int y   = rem >> 1;
        const int x0  = (rem & 1) << 7;

        // ---- conv: 3 groups (12 ch) per thread -> perc[px][24 words] ----
        {
            int xg = x0 + cpx;
            int swz = (cpx & 7) << 2;
#pragma unroll
            for (int gi = 0; gi < 3; gi++) {
                int g = cquad * 3 + gi;
                const float* src = (g < CNOISE)
                    ? (xin + ((size_t)b * CNOISE + g) * HW)
                    : (hin + ((size_t)b * (CIN - CNOISE) + (g - CNOISE)) * HW);
                float win[9];
#pragma unroll
                for (int dy = -1; dy <= 1; dy++)
#pragma unroll
                    for (int dx = -1; dx <= 1; dx++) {
                        int yy = y + dy, xx = xg + dx;
                        float v = 0.0f;
                        if (yy >= 0 && yy < HH && xx >= 0 && xx < WW)
                            v = __ldg(src + yy * WW + xx);
                        win[(dy + 1) * 3 + (dx + 1)] = v;
                    }
                float pv[4];
#pragma unroll
                for (int j = 0; j < 4; j++) {
                    int o = g * 4 + j;
                    float a = sm[OBP + o];
#pragma unroll
                    for (int q = 0; q < 9; q++)
                        a = fmaf(win[q], sm[OWP + o * 9 + q], a);
                    pv[j] = a;
                }
                uint2 pk = make_uint2(packh2(pv[0], pv[1]), packh2(pv[2], pv[3]));
                *(uint2*)(smU + OPH2 + cpx * 32 + ((2 * g) ^ swz)) = pk;
            }
        }
        __syncthreads();

        // ---- L1: 16ch x 64px per warp, K=48 (3 k16 steps) ----
        {
            float acc[8][4];
#pragma unroll
            for (int j = 0; j < 8; j++)
#pragma unroll
                for (int q = 0; q < 4; q++) acc[j][q] = 0.0f;
#pragma unroll
            for (int s = 0; s < 3; s++) {
                int kk = 8 * s + t4, kk4 = kk + 4;
                uint32_t a[4];
                a[0] = smU[OW1 + (cb + grp) * 32 + (kk ^ asw)];
                a[1] = smU[OW1 + (cb + grp + 8) * 32 + (kk ^ asw)];
                a[2] = smU[OW1 + (cb + grp) * 32 + (kk4 ^ asw)];
                a[3] = smU[OW1 + (cb + grp + 8) * 32 + (kk4 ^ asw)];
#pragma unroll
                for (int j = 0; j < 8; j++) {
                    int r = OPH2 + (pxb + 8 * j + grp) * 32;
                    mma16(acc[j], a, smU[r + (kk ^ asw)], smU[r + (kk4 ^ asw)]);
                }
            }
            __syncthreads();   // all perc reads done (h1 disjoint, but cheap & safe)
#pragma unroll
            for (int j = 0; j < 8; j++) {
                float v0 = fmaxf(acc[j][0] + b1v0, 0.0f);
                float v1 = fmaxf(acc[j][1] + b1v0, 0.0f);
                float v2 = fmaxf(acc[j][2] + b1v1, 0.0f);
                float v3 = fmaxf(acc[j][3] + b1v1, 0.0f);
                float o0 = __shfl_xor_sync(0xffffffffu, v0, 4);
                float o1 = __shfl_xor_sync(0xffffffffu, v1, 4);
                float o2 = __shfl_xor_sync(0xffffffffu, v2, 4);
                float o3 = __shfl_xor_sync(0xffffffffu, v3, 4);
                int px0 = pxb + 8 * j + 2 * t4;
                if ((grp & 1) == 0) {
                    int swz = (px0 & 7) << 2;
                    smU[OH1 + px0 * 64 + (widxL ^ swz)] = packh2(v0, o0);
                    smU[OH1 + px0 * 64 + ((widxL + 4) ^ swz)] = packh2(v2, o2);
                } else {
                    int px1 = px0 + 1, swz = (px1 & 7) << 2;
                    smU[OH1 + px1 * 64 + (widxL ^ swz)] = packh2(o1, v1);
                    smU[OH1 + px1 * 64 + ((widxL + 4) ^ swz)] = packh2(o3, v3);
                }
            }
        }
        __syncthreads();

        // ---- L2: 16ch x 64px per warp, K=128 (8 k16 steps) ----
        {
            float acc[8][4];
#pragma unroll
            for (int j = 0; j < 8; j++)
#pragma unroll
                for (int q = 0; q < 4; q++) acc[j][q] = 0.0f;
#pragma unroll
            for (int s = 0; s < 8; s++) {
                int kk = 8 * s + t4, kk4 = kk + 4;
                uint32_t a[4];
                a[0] = smU[OW2 + (cb + grp) * 64 + (kk ^ asw)];
                a[1] = smU[OW2 + (cb + grp + 8) * 64 + (kk ^ asw)];
                a[2] = smU[OW2 + (cb + grp) * 64 + (kk4 ^ asw)];
                a[3] = smU[OW2 + (cb + grp + 8) * 64 + (kk4 ^ asw)];
#pragma unroll
                for (int j = 0; j < 8; j++) {
                    int r = OH1 + (pxb + 8 * j + grp) * 64;
                    mma16(acc[j], a, smU[r + (kk ^ asw)], smU[r + (kk4 ^ asw)]);
                }
            }
            __syncthreads();   // h1 reads done before h2 overwrites perc region
#pragma unroll
            for (int j = 0; j < 8; j++) {
                float v0 = fmaxf(acc[j][0] + b2v0, 0.0f);
                float v1 = fmaxf(acc[j][1] + b2v0, 0.0f);
                float v2 = fmaxf(acc[j][2] + b2v1, 0.0f);
                float v3 = fmaxf(acc[j][3] + b2v1, 0.0f);
                float o0 = __shfl_xor_sync(0xffffffffu, v0, 4);
                float o1 = __shfl_xor_sync(0xffffffffu, v1, 4);
                float o2 = __shfl_xor_sync(0xffffffffu, v2, 4);
                float o3 = __shfl_xor_sync(0xffffffffu, v3, 4);
                int px0 = pxb + 8 * j + 2 * t4;
                if ((grp & 1) == 0) {
                    int swz = (px0 & 7) << 2;
                    smU[OPH2 + px0 * 64 + (widxL ^ swz)] = packh2(v0, o0);
                    smU[OPH2 + px0 * 64 + ((widxL + 4) ^ swz)] = packh2(v2, o2);
                } else {
                    int px1 = px0 + 1, swz = (px1 & 7) << 2;
                    smU[OPH2 + px1 * 64 + (widxL ^ swz)] = packh2(o1, v1);
                    smU[OPH2 + px1 * 64 + ((widxL + 4) ^ swz)] = packh2(o3, v3);
                }
            }
        }
        __syncthreads();

        // ---- L3: 12ch x 8px per warp, K=128; epilogue ----
        {
            float acc[4] = {0.0f, 0.0f, 0.0f, 0.0f};
#pragma unroll
            for (int s = 0; s < 8; s++) {
                int kk = 8 * s + t4, kk4 = kk + 4;
                uint32_t a[4];
                a[0] = smU[OW3 + grp * 64 + (kk ^ asw)];
                a[1] = smU[OW3 + (grp + 8) * 64 + (kk ^ asw)];
                a[2] = smU[OW3 + grp * 64 + (kk4 ^ asw)];
                a[3] = smU[OW3 + (grp + 8) * 64 + (kk4 ^ asw)];
                int r = OPH2 + (pxb3 + grp) * 64;
                mma16(acc, a, smU[r + (kk ^ asw)], smU[r + (kk4 ^ asw)]);
            }
            float* out_noise = dout + (size_t)BATCH * 9 * HW;
            float embv = (grp < CNOISE) ? __ldg(&g_emb[b * 3 + grp]) : 0.0f;
            int px0 = pxb3 + 2 * t4;
            size_t yx = (size_t)y * WW + x0 + px0;
            if (grp < CNOISE) {
                *(float2*)(out_noise + ((size_t)b * 3 + grp) * HW + yx) =
                    make_float2(acc[0] + embv, acc[1] + embv);
            } else {
                *(float2*)(dout + ((size_t)b * 9 + (grp - 3)) * HW + yx) =
                    make_float2(acc[0], acc[1]);
            }
            if (grp < 4) {
                *(float2*)(dout + ((size_t)b * 9 + (grp + 5)) * HW + yx) =
                    make_float2(acc[2], acc[3]);
            }
        }
        __syncthreads();   // h2 consumed before next tile's conv overwrites
    }
}

extern "C" void kernel_launch(void* const* d_in, const int* in_sizes, int n_in,
                              void* d_out, int out_size) {
    const float* x      = (const float*)d_in[0];
    const float* hid    = (const float*)d_in[1];
    const int*   t      = (const int*)d_in[2];
    const float* wp     = (const float*)d_in[3];
    const float* bp     = (const float*)d_in[4];
    const float* w1     = (const float*)d_in[5];
    const float* b1     = (const float*)d_in[6];
    const float* w2     = (const float*)d_in[7];
    const float* b2     = (const float*)d_in[8];
    const float* w3     = (const float*)d_in[9];
    const float* w_time = (const float*)d_in[10];
    const float* b_time = (const float*)d_in[11];
    float* out = (float*)d_out;

    cudaFuncSetAttribute(canet_main,
                         cudaFuncAttributeMaxDynamicSharedMemorySize,
                         SMEM_BYTES);

    int nsm = 148;
    if (cudaDeviceGetAttribute(&nsm, cudaDevAttrMultiProcessorCount, 0)
        != cudaSuccess || nsm <= 0)
        nsm = 148;

    emb_kernel<<<BATCH, TDIM>>>(t, w_time, b_time);
    canet_main<<<nsm, TPB, SMEM_BYTES>>>(
        x, hid, wp, bp, w1, b1, w2, b2, w3, out);
}

// round 6
// speedup vs baseline: 9.5196x; 1.2824x over previous
#include <cuda_runtime.h>
#include <cuda_fp16.h>
#include <cstdint>

#define HH 256
#define WW 256
#define BATCH 16
#define HW 65536
#define CIN 12
#define CNOISE 3
#define PERCC 48
#define HID 128
#define TDIM 256
#define TPB 512
#define TP 256
#define NTILES (BATCH * HW / TP)   // 4096  (tile = one image row)

// SMEM word (b32) offsets; fp16 packed pairs
#define OW2  0          // W2 [128 rows][64 words] swizzled, K-permuted
#define OW1  8192       // W1 [128 rows][32 words] (24 real) swizzled, natural K
#define OW3  12288      // W3 [16 rows][64 words] swizzled, K-permuted (rows 12-15 zero)
#define OWP  13312      // wp 48*9 fp32
#define OBP  13744      // bp 48
#define OB1  13792      // b1 128
#define OB2  13920      // b2 128
#define OH1  14048      // h1 [256 px][64 words] swizzled, K-permuted
#define OPH2 30432      // perc [256 px][32 words] natural / h2 [256 px][64 words] permuted
#define SMEM_WORDS 46816
#define SMEM_BYTES (SMEM_WORDS * 4)   // 187264

static __device__ __forceinline__ uint32_t packh2(float lo, float hi) {
    __half2 h = __floats2half2_rn(lo, hi);
    return *(uint32_t*)&h;
}

static __device__ __forceinline__ void mma16(float d[4], const uint32_t a[4],
                                             uint32_t b0, uint32_t b1) {
    asm volatile(
        "mma.sync.aligned.m16n8k16.row.col.f32.f16.f16.f32 "
        "{%0,%1,%2,%3}, {%4,%5,%6,%7}, {%8,%9}, {%0,%1,%2,%3};"
        : "+f"(d[0]), "+f"(d[1]), "+f"(d[2]), "+f"(d[3])
        : "r"(a[0]), "r"(a[1]), "r"(a[2]), "r"(a[3]), "r"(b0), "r"(b1));
}

__device__ float g_emb[BATCH * CNOISE];

// ---------------------------------------------------------------------------
__global__ void emb_kernel(const int* __restrict__ t,
                           const float* __restrict__ w_time,
                           const float* __restrict__ b_time) {
    __shared__ float ss[TDIM];
    int b = blockIdx.x, k = threadIdx.x;
    float tb = (float)t[b];
    int f = (k < TDIM / 2) ? k : (k - TDIM / 2);
    const double LN1E4 = 9.210340371976184;
    float invf = (float)exp(-LN1E4 * ((double)(2 * f) / 256.0));
    float ang = tb * invf;
    float pe = (float)((k < TDIM / 2) ? sin((double)ang) : cos((double)ang));
    ss[k] = pe / (1.0f + (float)exp(-(double)pe));
    __syncthreads();
    if (k < CNOISE) {
        float acc = b_time[k];
        for (int q = 0; q < TDIM; q++)
            acc = fmaf(ss[q], w_time[k * TDIM + q], acc);
        g_emb[b * CNOISE + k] = acc;
    }
}

// ---------------------------------------------------------------------------
// Persistent pipeline, fp16 m16n8k16, 16 warps, 256-px tiles.
// Warp tile L1/L2: 32ch x 64px (2 m-frags x 8 n-frags).
// Inter-layer channel pairing via K-permutation: fp16 word kw holds channels
// (16*(kw>>3) + (kw&7), +8) -- matches accumulator layout, no shfl needed.
// Weights of the consuming layer are staged with the same K-permutation.
// ---------------------------------------------------------------------------
__global__ void __launch_bounds__(TPB, 1)
canet_main(const float* __restrict__ xin, const float* __restrict__ hin,
           const float* __restrict__ wp, const float* __restrict__ bp,
           const float* __restrict__ w1, const float* __restrict__ b1,
           const float* __restrict__ w2, const float* __restrict__ b2,
           const float* __restrict__ w3, float* __restrict__ dout) {
    extern __shared__ float sm[];
    uint32_t* smU = (uint32_t*)sm;
    const int tx = threadIdx.x;

    // ---- one-time staging ----
    for (int i = tx; i < 1024; i += TPB) smU[OW3 + i] = 0u;
    __syncthreads();
    for (int i = tx; i < HID * 64; i += TPB) {       // W2, K-permuted
        int o = i >> 6, kw = i & 63;
        int kc = 16 * (kw >> 3) + (kw & 7);
        smU[OW2 + o * 64 + (kw ^ ((o & 7) << 2))] =
            packh2(w2[o * HID + kc], w2[o * HID + kc + 8]);
    }
    for (int i = tx; i < HID * 24; i += TPB) {       // W1, natural K
        int o = i / 24, kw = i % 24;
        smU[OW1 + o * 32 + (kw ^ ((o & 7) << 2))] =
            packh2(w1[o * PERCC + 2 * kw], w1[o * PERCC + 2 * kw + 1]);
    }
    for (int i = tx; i < CIN * 64; i += TPB) {       // W3, K-permuted
        int o = i >> 6, kw = i & 63;
        int kc = 16 * (kw >> 3) + (kw & 7);
        smU[OW3 + o * 64 + (kw ^ ((o & 7) << 2))] =
            packh2(w3[o * HID + kc], w3[o * HID + kc + 8]);
    }
    for (int i = tx; i < PERCC * 9; i += TPB) sm[OWP + i] = wp[i];
    if (tx < PERCC) sm[OBP + tx] = bp[tx];
    if (tx < HID) { sm[OB1 + tx] = b1[tx]; sm[OB2 + tx] = b2[tx]; }
    __syncthreads();

    const int w    = tx >> 5, lane = tx & 31;
    const int grp  = lane >> 2, t4 = lane & 3;
    const int asw  = grp << 2;
    const int cb   = (w & 3) * 32;       // channel base (32 ch per warp)
    const int pxb  = (w >> 2) * 64;      // pixel base (64 px per warp)
    const int pxb3 = w * 16;             // L3 pixel base (16 px per warp)

    float b1v[2][2], b2v[2][2];
#pragma unroll
    for (int i = 0; i < 2; i++) {
        b1v[i][0] = sm[OB1 + cb + 16 * i + grp];
        b1v[i][1] = sm[OB1 + cb + 16 * i + 8 + grp];
        b2v[i][0] = sm[OB2 + cb + 16 * i + grp];
        b2v[i][1] = sm[OB2 + cb + 16 * i + 8 + grp];
    }

    const int cpx   = tx & 255;          // conv pixel (full row)
    const int chalf = tx >> 8;           // conv groups [6h, 6h+6)

    for (int tile = blockIdx.x; tile < NTILES; tile += gridDim.x) {
        const int b = tile >> 8;
        const int y = tile & 255;

        // ---- conv: 6 groups (24 ch) per thread -> perc[px][24 words] ----
        {
            int swz = (cpx & 7) << 2;
#pragma unroll
            for (int gi = 0; gi < 6; gi++) {
                int g = chalf * 6 + gi;
                const float* src = (g < CNOISE)
                    ? (xin + ((size_t)b * CNOISE + g) * HW)
                    : (hin + ((size_t)b * (CIN - CNOISE) + (g - CNOISE)) * HW);
                float win[9];
#pragma unroll
                for (int dy = -1; dy <= 1; dy++)
#pragma unroll
                    for (int dx = -1; dx <= 1; dx++) {
                        int yy = y + dy, xx = cpx + dx;
                        float v = 0.0f;
                        if (yy >= 0 && yy < HH && xx >= 0 && xx < WW)
                            v = __ldg(src + yy * WW + xx);
                        win[(dy + 1) * 3 + (dx + 1)] = v;
                    }
                float pv[4];
#pragma unroll
                for (int j = 0; j < 4; j++) {
                    int o = g * 4 + j;
                    float a = sm[OBP + o];
#pragma unroll
                    for (int q = 0; q < 9; q++)
                        a = fmaf(win[q], sm[OWP + o * 9 + q], a);
                    pv[j] = a;
                }
                uint2 pk = make_uint2(packh2(pv[0], pv[1]), packh2(pv[2], pv[3]));
                *(uint2*)(smU + OPH2 + cpx * 32 + ((2 * g) ^ swz)) = pk;
            }
        }
        __syncthreads();

        // ---- L1: 32ch x 64px per warp, K=48 ----
        {
            float acc[2][8][4];
#pragma unroll
            for (int i = 0; i < 2; i++)
#pragma unroll
                for (int j = 0; j < 8; j++)
#pragma unroll
                    for (int q = 0; q < 4; q++) acc[i][j][q] = 0.0f;
#pragma unroll
            for (int s = 0; s < 3; s++) {
                int kks = (8 * s + t4) ^ asw, kk4s = (8 * s + t4 + 4) ^ asw;
                uint32_t a[2][4];
#pragma unroll
                for (int i = 0; i < 2; i++) {
                    int r = OW1 + (cb + 16 * i + grp) * 32;
                    a[i][0] = smU[r + kks];
                    a[i][1] = smU[r + 8 * 32 + kks];
                    a[i][2] = smU[r + kk4s];
                    a[i][3] = smU[r + 8 * 32 + kk4s];
                }
#pragma unroll
                for (int j = 0; j < 8; j++) {
                    int r = OPH2 + (pxb + 8 * j + grp) * 32;
                    uint32_t bb0 = smU[r + kks], bb1 = smU[r + kk4s];
                    mma16(acc[0][j], a[0], bb0, bb1);
                    mma16(acc[1][j], a[1], bb0, bb1);
                }
            }
            // relu + bias -> h1, permuted packing (v0,v2)=(ch,ch+8), no shfl
#pragma unroll
            for (int i = 0; i < 2; i++) {
                int wi = (cb >> 1) + 8 * i + grp;
#pragma unroll
                for (int j = 0; j < 8; j++) {
                    float v0 = fmaxf(acc[i][j][0] + b1v[i][0], 0.0f);
                    float v1 = fmaxf(acc[i][j][1] + b1v[i][0], 0.0f);
                    float v2 = fmaxf(acc[i][j][2] + b1v[i][1], 0.0f);
                    float v3 = fmaxf(acc[i][j][3] + b1v[i][1], 0.0f);
                    int px0 = pxb + 8 * j + 2 * t4;
                    smU[OH1 + px0 * 64 + (wi ^ ((px0 & 7) << 2))] = packh2(v0, v2);
                    smU[OH1 + (px0 + 1) * 64 + (wi ^ (((px0 + 1) & 7) << 2))] =
                        packh2(v1, v3);
                }
            }
        }
        __syncthreads();

        // ---- L2: 32ch x 64px per warp, K=128 ----
        {
            float acc[2][8][4];
#pragma unroll
            for (int i = 0; i < 2; i++)
#pragma unroll
                for (int j = 0; j < 8; j++)
#pragma unroll
                    for (int q = 0; q < 4; q++) acc[i][j][q] = 0.0f;
#pragma unroll
            for (int s = 0; s < 8; s++) {
                int kks = (8 * s + t4) ^ asw, kk4s = (8 * s + t4 + 4) ^ asw;
                uint32_t a[2][4];
#pragma unroll
                for (int i = 0; i < 2; i++) {
                    int r = OW2 + (cb + 16 * i + grp) * 64;
                    a[i][0] = smU[r + kks];
                    a[i][1] = smU[r + 8 * 64 + kks];
                    a[i][2] = smU[r + kk4s];
                    a[i][3] = smU[r + 8 * 64 + kk4s];
                }
#pragma unroll
                for (int j = 0; j < 8; j++) {
                    int r = OH1 + (pxb + 8 * j + grp) * 64;
                    uint32_t bb0 = smU[r + kks], bb1 = smU[r + kk4s];
                    mma16(acc[0][j], a[0], bb0, bb1);
                    mma16(acc[1][j], a[1], bb0, bb1);
                }
            }
            // relu + bias -> h2 (overlays perc; all perc reads done pre-L2 sync)
#pragma unroll
            for (int i = 0; i < 2; i++) {
                int wi = (cb >> 1) + 8 * i + grp;
#pragma unroll
                for (int j = 0; j < 8; j++) {
                    float v0 = fmaxf(acc[i][j][0] + b2v[i][0], 0.0f);
                    float v1 = fmaxf(acc[i][j][1] + b2v[i][0], 0.0f);
                    float v2 = fmaxf(acc[i][j][2] + b2v[i][1], 0.0f);
                    float v3 = fmaxf(acc[i][j][3] + b2v[i][1], 0.0f);
                    int px0 = pxb + 8 * j + 2 * t4;
                    smU[OPH2 + px0 * 64 + (wi ^ ((px0 & 7) << 2))] = packh2(v0, v2);
                    smU[OPH2 + (px0 + 1) * 64 + (wi ^ (((px0 + 1) & 7) << 2))] =
                        packh2(v1, v3);
                }
            }
        }
        __syncthreads();

        // ---- L3: 12ch x 16px per warp, K=128; epilogue ----
        {
            float acc[2][4];
#pragma unroll
            for (int j = 0; j < 2; j++)
#pragma unroll
                for (int q = 0; q < 4; q++) acc[j][q] = 0.0f;
#pragma unroll
            for (int s = 0; s < 8; s++) {
                int kks = (8 * s + t4) ^ asw, kk4s = (8 * s + t4 + 4) ^ asw;
                uint32_t a[4];
                a[0] = smU[OW3 + grp * 64 + kks];
                a[1] = smU[OW3 + (grp + 8) * 64 + kks];
                a[2] = smU[OW3 + grp * 64 + kk4s];
                a[3] = smU[OW3 + (grp + 8) * 64 + kk4s];
#pragma unroll
                for (int j = 0; j < 2; j++) {
                    int r = OPH2 + (pxb3 + 8 * j + grp) * 64;
                    mma16(acc[j], a, smU[r + kks], smU[r + kk4s]);
                }
            }
            float* out_noise = dout + (size_t)BATCH * 9 * HW;
            float embv = (grp < CNOISE) ? __ldg(&g_emb[b * 3 + grp]) : 0.0f;
#pragma unroll
            for (int j = 0; j < 2; j++) {
                int px0 = pxb3 + 8 * j + 2 * t4;
                size_t yx = (size_t)y * WW + px0;
                if (grp < CNOISE) {
                    *(float2*)(out_noise + ((size_t)b * 3 + grp) * HW + yx) =
                        make_float2(acc[j][0] + embv, acc[j][1] + embv);
                } else {
                    *(float2*)(dout + ((size_t)b * 9 + (grp - 3)) * HW + yx) =
                        make_float2(acc[j][0], acc[j][1]);
                }
                if (grp < 4) {
                    *(float2*)(dout + ((size_t)b * 9 + (grp + 5)) * HW + yx) =
                        make_float2(acc[j][2], acc[j][3]);
                }
            }
        }
        __syncthreads();   // h2 consumed before next tile's conv overwrites
    }
}

extern "C" void kernel_launch(void* const* d_in, const int* in_sizes, int n_in,
                              void* d_out, int out_size) {
    const float* x      = (const float*)d_in[0];
    const float* hid    = (const float*)d_in[1];
    const int*   t      = (const int*)d_in[2];
    const float* wp     = (const float*)d_in[3];
    const float* bp     = (const float*)d_in[4];
    const float* w1     = (const float*)d_in[5];
    const float* b1     = (const float*)d_in[6];
    const float* w2     = (const float*)d_in[7];
    const float* b2     = (const float*)d_in[8];
    const float* w3     = (const float*)d_in[9];
    const float* w_time = (const float*)d_in[10];
    const float* b_time = (const float*)d_in[11];
    float* out = (float*)d_out;

    cudaFuncSetAttribute(canet_main,
                         cudaFuncAttributeMaxDynamicSharedMemorySize,
                         SMEM_BYTES);

    int nsm = 148;
    if (cudaDeviceGetAttribute(&nsm, cudaDevAttrMultiProcessorCount, 0)
        != cudaSuccess || nsm <= 0)
        nsm = 148;

    emb_kernel<<<BATCH, TDIM>>>(t, w_time, b_time);
    canet_main<<<nsm, TPB, SMEM_BYTES>>>(
        x, hid, wp, bp, w1, b1, w2, b2, w3, out);
}

// round 7
// speedup vs baseline: 10.2219x; 1.0738x over previous
#include <cuda_runtime.h>
#include <cuda_fp16.h>
#include <cstdint>

#define HH 256
#define WW 256
#define BATCH 16
#define HW 65536
#define CIN 12
#define CNOISE 3
#define PERCC 48
#define HID 128
#define TDIM 256
#define TPB 512
#define TP 256
#define NTILES (BATCH * HW / TP)   // 4096 (tile = one image row)

// SMEM word (b32) offsets; fp16 packed pairs
#define OW2  0          // W2 [128 rows][64 words] swizzled, K-permuted
#define OW1  8192       // W1 [128 rows][32 words] (24 real) swizzled, natural K
#define OW3  12288      // W3 [16 rows][64 words] swizzled, K-permuted (rows 12-15 zero)
#define OWP  13312      // wp 48*9 fp32
#define OBP  13744      // bp 48
#define OB1  13792      // b1 128
#define OB2  13920      // b2 128
#define OH1  14048      // h1 [256 px][64 words] swizzled, K-permuted
#define OPH2 30432      // perc [256 px][32 words] natural / h2 [256 px][64 words] permuted
#define SMEM_WORDS 46816
#define SMEM_BYTES (SMEM_WORDS * 4)   // 187264

static __device__ __forceinline__ uint32_t packh2(float lo, float hi) {
    __half2 h = __floats2half2_rn(lo, hi);
    return *(uint32_t*)&h;
}

static __device__ __forceinline__ uint32_t smem_u32(const void* p) {
    uint32_t a;
    asm("{ .reg .u64 t; cvta.to.shared.u64 t, %1; cvt.u32.u64 %0, t; }"
        : "=r"(a) : "l"(p));
    return a;
}

static __device__ __forceinline__ void mma16(float d[4], const uint32_t a[4],
                                             uint32_t b0, uint32_t b1) {
    asm volatile(
        "mma.sync.aligned.m16n8k16.row.col.f32.f16.f16.f32 "
        "{%0,%1,%2,%3}, {%4,%5,%6,%7}, {%8,%9}, {%0,%1,%2,%3};"
        : "+f"(d[0]), "+f"(d[1]), "+f"(d[2]), "+f"(d[3])
        : "r"(a[0]), "r"(a[1]), "r"(a[2]), "r"(a[3]), "r"(b0), "r"(b1));
}

#define LDSM4(r, a) \
    asm volatile("ldmatrix.sync.aligned.m8n8.x4.shared.b16 {%0,%1,%2,%3}, [%4];" \
        : "=r"((r)[0]), "=r"((r)[1]), "=r"((r)[2]), "=r"((r)[3]) : "r"(a))

__device__ float g_emb[BATCH * CNOISE];

// ---------------------------------------------------------------------------
__global__ void emb_kernel(const int* __restrict__ t,
                           const float* __restrict__ w_time,
                           const float* __restrict__ b_time) {
    __shared__ float ss[TDIM];
    int b = blockIdx.x, k = threadIdx.x;
    float tb = (float)t[b];
    int f = (k < TDIM / 2) ? k : (k - TDIM / 2);
    const double LN1E4 = 9.210340371976184;
    float invf = (float)exp(-LN1E4 * ((double)(2 * f) / 256.0));
    float ang = tb * invf;
    float pe = (float)((k < TDIM / 2) ? sin((double)ang) : cos((double)ang));
    ss[k] = pe / (1.0f + (float)exp(-(double)pe));
    __syncthreads();
    if (k < CNOISE) {
        float acc = b_time[k];
        for (int q = 0; q < TDIM; q++)
            acc = fmaf(ss[q], w_time[k * TDIM + q], acc);
        g_emb[b * CNOISE + k] = acc;
    }
}

// ---------------------------------------------------------------------------
// Persistent pipeline, fp16 m16n8k16, 16 warps, 256-px tiles.
// All GEMM fragment loads via ldmatrix.x4 with tile-invariant base addresses.
// ---------------------------------------------------------------------------
__global__ void __launch_bounds__(TPB, 1)
canet_main(const float* __restrict__ xin, const float* __restrict__ hin,
           const float* __restrict__ wp, const float* __restrict__ bp,
           const float* __restrict__ w1, const float* __restrict__ b1,
           const float* __restrict__ w2, const float* __restrict__ b2,
           const float* __restrict__ w3, float* __restrict__ dout) {
    extern __shared__ float sm[];
    uint32_t* smU = (uint32_t*)sm;
    const int tx = threadIdx.x;

    // ---- one-time staging ----
    for (int i = tx; i < 1024; i += TPB) smU[OW3 + i] = 0u;
    __syncthreads();
    for (int i = tx; i < HID * 64; i += TPB) {       // W2, K-permuted
        int o = i >> 6, kw = i & 63;
        int kc = 16 * (kw >> 3) + (kw & 7);
        smU[OW2 + o * 64 + (kw ^ ((o & 7) << 2))] =
            packh2(w2[o * HID + kc], w2[o * HID + kc + 8]);
    }
    for (int i = tx; i < HID * 24; i += TPB) {       // W1, natural K
        int o = i / 24, kw = i % 24;
        smU[OW1 + o * 32 + (kw ^ ((o & 7) << 2))] =
            packh2(w1[o * PERCC + 2 * kw], w1[o * PERCC + 2 * kw + 1]);
    }
    for (int i = tx; i < CIN * 64; i += TPB) {       // W3, K-permuted
        int o = i >> 6, kw = i & 63;
        int kc = 16 * (kw >> 3) + (kw & 7);
        smU[OW3 + o * 64 + (kw ^ ((o & 7) << 2))] =
            packh2(w3[o * HID + kc], w3[o * HID + kc + 8]);
    }
    for (int i = tx; i < PERCC * 9; i += TPB) sm[OWP + i] = wp[i];
    if (tx < PERCC) sm[OBP + tx] = bp[tx];
    if (tx < HID) { sm[OB1 + tx] = b1[tx]; sm[OB2 + tx] = b2[tx]; }
    __syncthreads();

    const uint32_t sbase = smem_u32(sm);
    const int w    = tx >> 5, lane = tx & 31;
    const int grp  = lane >> 2, t4 = lane & 3;
    const int cb   = (w & 3) * 32;       // channel base (32 ch per warp)
    const int pxb  = (w >> 2) * 64;      // pixel base (64 px per warp)
    const int pxb3 = w * 16;             // L3 pixel base

    // ---- ldmatrix per-lane invariant addressing ----
    const int swlo = (lane & 1) << 2;          // swizzle bit 2
    const int swhi = (lane & 6) << 2;          // swizzle bits 3-4
    const int cA   = ((lane >> 4) << 2) ^ swlo;    // A word base (k-half select)
    const int cB   = (((lane >> 3) & 1) << 2) ^ swlo;  // B word base
    const int lr   = lane & 15;                    // A row-in-block
    const int bRow = (lane & 7) + ((lane >> 4) << 3);  // B row (covers 2 n-frags)

    uint32_t aW1[2], aW2[2], bP[4], bH1[4];
#pragma unroll
    for (int i = 0; i < 2; i++) {
        aW1[i] = sbase + 4 * (OW1 + (cb + 16 * i + lr) * 32 + cA);
        aW2[i] = sbase + 4 * (OW2 + (cb + 16 * i + lr) * 64 + cA);
    }
#pragma unroll
    for (int j = 0; j < 4; j++) {
        bP[j]  = sbase + 4 * (OPH2 + (pxb + 16 * j + bRow) * 32 + cB);
        bH1[j] = sbase + 4 * (OH1 + (pxb + 16 * j + bRow) * 64 + cB);
    }
    const uint32_t aW3 = sbase + 4 * (OW3 + lr * 64 + cA);
    const uint32_t bH2 = sbase + 4 * (OPH2 + (pxb3 + bRow) * 64 + cB);

    float b1v[2][2], b2v[2][2];
#pragma unroll
    for (int i = 0; i < 2; i++) {
        b1v[i][0] = sm[OB1 + cb + 16 * i + grp];
        b1v[i][1] = sm[OB1 + cb + 16 * i + 8 + grp];
        b2v[i][0] = sm[OB2 + cb + 16 * i + grp];
        b2v[i][1] = sm[OB2 + cb + 16 * i + 8 + grp];
    }

    const int cpx   = tx & 255;
    const int chalf = tx >> 8;

    for (int tile = blockIdx.x; tile < NTILES; tile += gridDim.x) {
        const int b = tile >> 8;
        const int y = tile & 255;

        // ---- conv: 6 groups (24 ch) per thread -> perc[px][24 words] ----
        {
            int swz = (cpx & 7) << 2;
#pragma unroll
            for (int gi = 0; gi < 6; gi++) {
                int g = chalf * 6 + gi;
                const float* src = (g < CNOISE)
                    ? (xin + ((size_t)b * CNOISE + g) * HW)
                    : (hin + ((size_t)b * (CIN - CNOISE) + (g - CNOISE)) * HW);
                float win[9];
#pragma unroll
                for (int dy = -1; dy <= 1; dy++)
#pragma unroll
                    for (int dx = -1; dx <= 1; dx++) {
                        int yy = y + dy, xx = cpx + dx;
                        float v = 0.0f;
                        if (yy >= 0 && yy < HH && xx >= 0 && xx < WW)
                            v = __ldg(src + yy * WW + xx);
                        win[(dy + 1) * 3 + (dx + 1)] = v;
                    }
                float pv[4];
#pragma unroll
                for (int j = 0; j < 4; j++) {
                    int o = g * 4 + j;
                    float a = sm[OBP + o];
#pragma unroll
                    for (int q = 0; q < 9; q++)
                        a = fmaf(win[q], sm[OWP + o * 9 + q], a);
                    pv[j] = a;
                }
                uint2 pk = make_uint2(packh2(pv[0], pv[1]), packh2(pv[2], pv[3]));
                *(uint2*)(smU + OPH2 + cpx * 32 + ((2 * g) ^ swz)) = pk;
            }
        }
        __syncthreads();

        // ---- L1: 32ch x 64px per warp, K=48 ----
        {
            float acc[2][8][4];
#pragma unroll
            for (int i = 0; i < 2; i++)
#pragma unroll
                for (int j = 0; j < 8; j++)
#pragma unroll
                    for (int q = 0; q < 4; q++) acc[i][j][q] = 0.0f;
#pragma unroll
            for (int s = 0; s < 3; s++) {
                uint32_t ds = (uint32_t)(((8 * s) ^ swhi) << 2);
                uint32_t a0[4], a1[4], bb[4][4];
                LDSM4(a0, aW1[0] + ds);
                LDSM4(a1, aW1[1] + ds);
#pragma unroll
                for (int jj = 0; jj < 4; jj++) LDSM4(bb[jj], bP[jj] + ds);
#pragma unroll
                for (int jj = 0; jj < 4; jj++) {
                    mma16(acc[0][2 * jj],     a0, bb[jj][0], bb[jj][1]);
                    mma16(acc[1][2 * jj],     a1, bb[jj][0], bb[jj][1]);
                    mma16(acc[0][2 * jj + 1], a0, bb[jj][2], bb[jj][3]);
                    mma16(acc[1][2 * jj + 1], a1, bb[jj][2], bb[jj][3]);
                }
            }
            // relu + bias -> h1, K-permuted packing (ch, ch+8), no shfl
#pragma unroll
            for (int i = 0; i < 2; i++) {
                int wi = (cb >> 1) + 8 * i + grp;
#pragma unroll
                for (int j = 0; j < 8; j++) {
                    float v0 = fmaxf(acc[i][j][0] + b1v[i][0], 0.0f);
                    float v1 = fmaxf(acc[i][j][1] + b1v[i][0], 0.0f);
                    float v2 = fmaxf(acc[i][j][2] + b1v[i][1], 0.0f);
                    float v3 = fmaxf(acc[i][j][3] + b1v[i][1], 0.0f);
                    int px0 = pxb + 8 * j + 2 * t4;
                    smU[OH1 + px0 * 64 + (wi ^ ((px0 & 7) << 2))] = packh2(v0, v2);
                    smU[OH1 + (px0 + 1) * 64 + (wi ^ (((px0 + 1) & 7) << 2))] =
                        packh2(v1, v3);
                }
            }
        }
        __syncthreads();

        // ---- L2: 32ch x 64px per warp, K=128 ----
        {
            float acc[2][8][4];
#pragma unroll
            for (int i = 0; i < 2; i++)
#pragma unroll
                for (int j = 0; j < 8; j++)
#pragma unroll
                    for (int q = 0; q < 4; q++) acc[i][j][q] = 0.0f;
#pragma unroll
            for (int s = 0; s < 8; s++) {
                uint32_t ds = (uint32_t)(((8 * s) ^ swhi) << 2);
                uint32_t a0[4], a1[4], bb[4][4];
                LDSM4(a0, aW2[0] + ds);
                LDSM4(a1, aW2[1] + ds);
#pragma unroll
                for (int jj = 0; jj < 4; jj++) LDSM4(bb[jj], bH1[jj] + ds);
#pragma unroll
                for (int jj = 0; jj < 4; jj++) {
                    mma16(acc[0][2 * jj],     a0, bb[jj][0], bb[jj][1]);
                    mma16(acc[1][2 * jj],     a1, bb[jj][0], bb[jj][1]);
                    mma16(acc[0][2 * jj + 1], a0, bb[jj][2], bb[jj][3]);
                    mma16(acc[1][2 * jj + 1], a1, bb[jj][2], bb[jj][3]);
                }
            }
            // relu + bias -> h2 (overlays perc; perc reads finished pre-L2 sync)
#pragma unroll
            for (int i = 0; i < 2; i++) {
                int wi = (cb >> 1) + 8 * i + grp;
#pragma unroll
                for (int j = 0; j < 8; j++) {
                    float v0 = fmaxf(acc[i][j][0] + b2v[i][0], 0.0f);
                    float v1 = fmaxf(acc[i][j][1] + b2v[i][0], 0.0f);
                    float v2 = fmaxf(acc[i][j][2] + b2v[i][1], 0.0f);
                    float v3 = fmaxf(acc[i][j][3] + b2v[i][1], 0.0f);
                    int px0 = pxb + 8 * j + 2 * t4;
                    smU[OPH2 + px0 * 64 + (wi ^ ((px0 & 7) << 2))] = packh2(v0, v2);
                    smU[OPH2 + (px0 + 1) * 64 + (wi ^ (((px0 + 1) & 7) << 2))] =
                        packh2(v1, v3);
                }
            }
        }
        __syncthreads();

        // ---- L3: 12ch x 16px per warp, K=128; epilogue ----
        {
            float acc[2][4];
#pragma unroll
            for (int j = 0; j < 2; j++)
#pragma unroll
                for (int q = 0; q < 4; q++) acc[j][q] = 0.0f;
#pragma unroll
            for (int s = 0; s < 8; s++) {
                uint32_t ds = (uint32_t)(((8 * s) ^ swhi) << 2);
                uint32_t a[4], bb[4];
                LDSM4(a, aW3 + ds);
                LDSM4(bb, bH2 + ds);
                mma16(acc[0], a, bb[0], bb[1]);
                mma16(acc[1], a, bb[2], bb[3]);
            }
            float* out_noise = dout + (size_t)BATCH * 9 * HW;
            float embv = (grp < CNOISE) ? __ldg(&g_emb[b * 3 + grp]) : 0.0f;
#pragma unroll
            for (int j = 0; j < 2; j++) {
                int px0 = pxb3 + 8 * j + 2 * t4;
                size_t yx = (size_t)y * WW + px0;
                if (grp < CNOISE) {
                    *(float2*)(out_noise + ((size_t)b * 3 + grp) * HW + yx) =
                        make_float2(acc[j][0] + embv, acc[j][1] + embv);
                } else {
                    *(float2*)(dout + ((size_t)b * 9 + (grp - 3)) * HW + yx) =
                        make_float2(acc[j][0], acc[j][1]);
                }
                if (grp < 4) {
                    *(float2*)(dout + ((size_t)b * 9 + (grp + 5)) * HW + yx) =
                        make_float2(acc[j][2], acc[j][3]);
                }
            }
        }
        __syncthreads();   // h2 consumed before next tile's conv overwrites
    }
}

extern "C" void kernel_launch(void* const* d_in, const int* in_sizes, int n_in,
                              void* d_out, int out_size) {
    const float* x      = (const float*)d_in[0];
    const float* hid    = (const float*)d_in[1];
    const int*   t      = (const int*)d_in[2];
    const float* wp     = (const float*)d_in[3];
    const float* bp     = (const float*)d_in[4];
    const float* w1     = (const float*)d_in[5];
    const float* b1     = (const float*)d_in[6];
    const float* w2     = (const float*)d_in[7];
    const float* b2     = (const float*)d_in[8];
    const float* w3     = (const float*)d_in[9];
    const float* w_time = (const float*)d_in[10];
    const float* b_time = (const float*)d_in[11];
    float* out = (float*)d_out;

    cudaFuncSetAttribute(canet_main,
                         cudaFuncAttributeMaxDynamicSharedMemorySize,
                         SMEM_BYTES);

    int nsm = 148;
    if (cudaDeviceGetAttribute(&nsm, cudaDevAttrMultiProcessorCount, 0)
        != cudaSuccess || nsm <= 0)
        nsm = 148;

    emb_kernel<<<BATCH, TDIM>>>(t, w_time, b_time);
    canet_main<<<nsm, TPB, SMEM_BYTES>>>(
        x, hid, wp, bp, w1, b1, w2, b2, w3, out);
}

// round 8
// speedup vs baseline: 10.5672x; 1.0338x over previous
#include <cuda_runtime.h>
#include <cuda_fp16.h>
#include <cstdint>

#define HH 256
#define WW 256
#define BATCH 16
#define HW 65536
#define CIN 12
#define CNOISE 3
#define PERCC 48
#define HID 128
#define TDIM 256
#define TPB 512
#define TP 256
#define NTILES (BATCH * HW / TP)   // 4096 (tile = one image row)

// SMEM word (b32) offsets
#define OW2   0       // W2 [128 rows][64 words] swizzled, K-permuted fp16-pairs
#define OW1   8192    // W1 [128 rows][32 words] (24 real) swizzled
#define OW3   12288   // W3 [16 rows][64 words] swizzled, K-permuted (rows 12-15 zero)
#define OWPK  13312   // conv weights packed: [12 grp][9 q][4 floats]
#define OBPK  13744   // conv bias packed: [12 grp][4 floats]
#define OB1   13792   // b1 128 fp32
#define OB2   13920   // b2 128 fp32
#define OH1   14048   // h region [256 px][64 words]: h1, then h2 (overwritten)
#define OPH2  30432   // perc double buffer: 2 x [256 px][32 words]
#define PERCW 8192
#define SMEM_WORDS 46816
#define SMEM_BYTES (SMEM_WORDS * 4)   // 187264

typedef unsigned long long ull;

#define FMA2(d, a, b) \
    asm("fma.rn.f32x2 %0, %1, %2, %0;" : "+l"(d) : "l"(a), "l"(b))
#define PACKF(out, lo, hi) \
    asm("mov.b64 %0, {%1, %2};" : "=l"(out) : "f"(lo), "f"(hi))
#define UNPACKF(lo, hi, in) \
    asm("mov.b64 {%0, %1}, %2;" : "=f"(lo), "=f"(hi) : "l"(in))

static __device__ __forceinline__ uint32_t packh2(float lo, float hi) {
    __half2 h = __floats2half2_rn(lo, hi);
    return *(uint32_t*)&h;
}

static __device__ __forceinline__ uint32_t smem_u32(const void* p) {
    uint32_t a;
    asm("{ .reg .u64 t; cvta.to.shared.u64 t, %1; cvt.u32.u64 %0, t; }"
        : "=r"(a) : "l"(p));
    return a;
}

static __device__ __forceinline__ void mma16(float d[4], const uint32_t a[4],
                                             uint32_t b0, uint32_t b1) {
    asm volatile(
        "mma.sync.aligned.m16n8k16.row.col.f32.f16.f16.f32 "
        "{%0,%1,%2,%3}, {%4,%5,%6,%7}, {%8,%9}, {%0,%1,%2,%3};"
        : "+f"(d[0]), "+f"(d[1]), "+f"(d[2]), "+f"(d[3])
        : "r"(a[0]), "r"(a[1]), "r"(a[2]), "r"(a[3]), "r"(b0), "r"(b1));
}

#define LDSM4(r, a) \
    asm volatile("ldmatrix.sync.aligned.m8n8.x4.shared.b16 {%0,%1,%2,%3}, [%4];" \
        : "=r"((r)[0]), "=r"((r)[1]), "=r"((r)[2]), "=r"((r)[3]) : "r"(a))

__device__ float g_emb[BATCH * CNOISE];

// ---------------------------------------------------------------------------
__global__ void emb_kernel(const int* __restrict__ t,
                           const float* __restrict__ w_time,
                           const float* __restrict__ b_time) {
    __shared__ float ss[TDIM];
    int b = blockIdx.x, k = threadIdx.x;
    float tb = (float)t[b];
    int f = (k < TDIM / 2) ? k : (k - TDIM / 2);
    const double LN1E4 = 9.210340371976184;
    float invf = (float)exp(-LN1E4 * ((double)(2 * f) / 256.0));
    float ang = tb * invf;
    float pe = (float)((k < TDIM / 2) ? sin((double)ang) : cos((double)ang));
    ss[k] = pe / (1.0f + (float)exp(-(double)pe));
    __syncthreads();
    if (k < CNOISE) {
        float acc = b_time[k];
        for (int q = 0; q < TDIM; q++)
            acc = fmaf(ss[q], w_time[k * TDIM + q], acc);
        g_emb[b * CNOISE + k] = acc;
    }
}

// ---------------------------------------------------------------------------
// Depthwise conv for one tile row -> perc buffer (word base dstW).
// Packed-pair math: per group 9 LDS.128(broadcast) + 18 FMA2 replaces
// 36 LDS.32 + 36 FFMA. Window loads batched first for MLP.
// ---------------------------------------------------------------------------
static __device__ __forceinline__ void conv_tile(
    const float* __restrict__ xin, const float* __restrict__ hin,
    const float* sm, uint32_t* smU, int b, int y, int dstW,
    int cpx, int chalf) {
    float win[6][9];
#pragma unroll
    for (int gi = 0; gi < 6; gi++) {
        int g = chalf * 6 + gi;
        const float* src = (g < CNOISE)
            ? (xin + ((size_t)b * CNOISE + g) * HW)
            : (hin + ((size_t)b * (CIN - CNOISE) + (g - CNOISE)) * HW);
#pragma unroll
        for (int dy = -1; dy <= 1; dy++)
#pragma unroll
            for (int dx = -1; dx <= 1; dx++) {
                int yy = y + dy, xx = cpx + dx;
                float v = 0.0f;
                if (yy >= 0 && yy < HH && xx >= 0 && xx < WW)
                    v = __ldg(src + yy * WW + xx);
                win[gi][(dy + 1) * 3 + (dx + 1)] = v;
            }
    }
    int swz = (cpx & 7) << 2;
#pragma unroll
    for (int gi = 0; gi < 6; gi++) {
        int g = chalf * 6 + gi;
        ulonglong2 bb = *(const ulonglong2*)(sm + OBPK + g * 4);
        ull a01 = bb.x, a23 = bb.y;
#pragma unroll
        for (int q = 0; q < 9; q++) {
            ull wd;
            PACKF(wd, win[gi][q], win[gi][q]);
            ulonglong2 ww = *(const ulonglong2*)(sm + OWPK + (g * 9 + q) * 4);
            FMA2(a01, wd, ww.x);
            FMA2(a23, wd, ww.y);
        }
        float a0, a1, a2, a3;
        UNPACKF(a0, a1, a01);
        UNPACKF(a2, a3, a23);
        *(uint2*)(smU + dstW + cpx * 32 + ((2 * g) ^ swz)) =
            make_uint2(packh2(a0, a1), packh2(a2, a3));
    }
}

// ---------------------------------------------------------------------------
// Persistent pipeline, fp16 m16n8k16, 16 warps, 256-px tiles.
// Phases per tile: [L1 mma+store] [L2 mma] [L2 store] [L3 + conv(next tile)]
// perc double-buffered; h1/h2 share one region (extra bar covers overwrite).
// ---------------------------------------------------------------------------
__global__ void __launch_bounds__(TPB, 1)
canet_main(const float* __restrict__ xin, const float* __restrict__ hin,
           const float* __restrict__ wp, const float* __restrict__ bp,
           const float* __restrict__ w1, const float* __restrict__ b1,
           const float* __restrict__ w2, const float* __restrict__ b2,
           const float* __restrict__ w3, float* __restrict__ dout) {
    extern __shared__ float sm[];
    uint32_t* smU = (uint32_t*)sm;
    const int tx = threadIdx.x;

    // ---- one-time staging ----
    for (int i = tx; i < 1024; i += TPB) smU[OW3 + i] = 0u;
    __syncthreads();
    for (int i = tx; i < HID * 64; i += TPB) {       // W2, K-permuted
        int o = i >> 6, kw = i & 63;
        int kc = 16 * (kw >> 3) + (kw & 7);
        smU[OW2 + o * 64 + (kw ^ ((o & 7) << 2))] =
            packh2(w2[o * HID + kc], w2[o * HID + kc + 8]);
    }
    for (int i = tx; i < HID * 24; i += TPB) {       // W1, natural K
        int o = i / 24, kw = i % 24;
        smU[OW1 + o * 32 + (kw ^ ((o & 7) << 2))] =
            packh2(w1[o * PERCC + 2 * kw], w1[o * PERCC + 2 * kw + 1]);
    }
    for (int i = tx; i < CIN * 64; i += TPB) {       // W3, K-permuted
        int o = i >> 6, kw = i & 63;
        int kc = 16 * (kw >> 3) + (kw & 7);
        smU[OW3 + o * 64 + (kw ^ ((o & 7) << 2))] =
            packh2(w3[o * HID + kc], w3[o * HID + kc + 8]);
    }
    for (int i = tx; i < 108; i += TPB) {            // conv weights packed
        int g = i / 9, q = i % 9;
        float4 v = make_float4(wp[(4 * g + 0) * 9 + q], wp[(4 * g + 1) * 9 + q],
                               wp[(4 * g + 2) * 9 + q], wp[(4 * g + 3) * 9 + q]);
        *(float4*)(sm + OWPK + i * 4) = v;
    }
    if (tx < 12)
        *(float4*)(sm + OBPK + tx * 4) =
            make_float4(bp[4 * tx], bp[4 * tx + 1], bp[4 * tx + 2], bp[4 * tx + 3]);
    if (tx < HID) { sm[OB1 + tx] = b1[tx]; sm[OB2 + tx] = b2[tx]; }
    __syncthreads();

    const uint32_t sbase = smem_u32(sm);
    const int w    = tx >> 5, lane = tx & 31;
    const int grp  = lane >> 2, t4 = lane & 3;
    const int cb   = (w & 3) * 32;       // channel base (32 ch per warp)
    const int pxb  = (w >> 2) * 64;      // pixel base (64 px per warp)
    const int pxb3 = w * 16;             // L3 pixel base

    // ---- ldmatrix per-lane invariant addressing ----
    const int swlo = (lane & 1) << 2;
    const int swhi = (lane & 6) << 2;
    const int cA   = ((lane >> 4) << 2) ^ swlo;
    const int cB   = (((lane >> 3) & 1) << 2) ^ swlo;
    const int lr   = lane & 15;
    const int bRow = (lane & 7) + ((lane >> 4) << 3);

    uint32_t aW1[2], aW2[2], bP0[4], bH1[4];
#pragma unroll
    for (int i = 0; i < 2; i++) {
        aW1[i] = sbase + 4 * (OW1 + (cb + 16 * i + lr) * 32 + cA);
        aW2[i] = sbase + 4 * (OW2 + (cb + 16 * i + lr) * 64 + cA);
    }
#pragma unroll
    for (int j = 0; j < 4; j++) {
        bP0[j] = sbase + 4 * (OPH2 + (pxb + 16 * j + bRow) * 32 + cB);
        bH1[j] = sbase + 4 * (OH1 + (pxb + 16 * j + bRow) * 64 + cB);
    }
    const uint32_t aW3 = sbase + 4 * (OW3 + lr * 64 + cA);
    const uint32_t bH2 = sbase + 4 * (OH1 + (pxb3 + bRow) * 64 + cB);

    float b1v[2][2], b2v[2][2];
#pragma unroll
    for (int i = 0; i < 2; i++) {
        b1v[i][0] = sm[OB1 + cb + 16 * i + grp];
        b1v[i][1] = sm[OB1 + cb + 16 * i + 8 + grp];
        b2v[i][0] = sm[OB2 + cb + 16 * i + grp];
        b2v[i][1] = sm[OB2 + cb + 16 * i + 8 + grp];
    }

    const int cpx   = tx & 255;
    const int chalf = tx >> 8;

    // ---- prologue: conv for this CTA's first tile into buffer 0 ----
    {
        int t0 = blockIdx.x;
        conv_tile(xin, hin, sm, smU, t0 >> 8, t0 & 255, OPH2, cpx, chalf);
    }
    __syncthreads();
    int par = 0;

    for (int tile = blockIdx.x; tile < NTILES; tile += gridDim.x) {
        const int b = tile >> 8;
        const int y = tile & 255;
        const uint32_t pofs = (uint32_t)par << 15;   // 8192 words = 32768 B

        // ---- L1: 32ch x 64px per warp, K=48; relu-store -> h region ----
        {
            float acc[2][8][4];
#pragma unroll
            for (int i = 0; i < 2; i++)
#pragma unroll
                for (int j = 0; j < 8; j++)
#pragma unroll
                    for (int q = 0; q < 4; q++) acc[i][j][q] = 0.0f;
#pragma unroll
            for (int s = 0; s < 3; s++) {
                uint32_t ds = (uint32_t)(((8 * s) ^ swhi) << 2);
                uint32_t a0[4], a1[4], bb[4][4];
                LDSM4(a0, aW1[0] + ds);
                LDSM4(a1, aW1[1] + ds);
#pragma unroll
                for (int jj = 0; jj < 4; jj++) LDSM4(bb[jj], bP0[jj] + pofs + ds);
#pragma unroll
                for (int jj = 0; jj < 4; jj++) {
                    mma16(acc[0][2 * jj],     a0, bb[jj][0], bb[jj][1]);
                    mma16(acc[1][2 * jj],     a1, bb[jj][0], bb[jj][1]);
                    mma16(acc[0][2 * jj + 1], a0, bb[jj][2], bb[jj][3]);
                    mma16(acc[1][2 * jj + 1], a1, bb[jj][2], bb[jj][3]);
                }
            }
#pragma unroll
            for (int i = 0; i < 2; i++) {
                int wi = (cb >> 1) + 8 * i + grp;
#pragma unroll
                for (int j = 0; j < 8; j++) {
                    float v0 = fmaxf(acc[i][j][0] + b1v[i][0], 0.0f);
                    float v1 = fmaxf(acc[i][j][1] + b1v[i][0], 0.0f);
                    float v2 = fmaxf(acc[i][j][2] + b1v[i][1], 0.0f);
                    float v3 = fmaxf(acc[i][j][3] + b1v[i][1], 0.0f);
                    int px0 = pxb + 8 * j + 2 * t4;
                    smU[OH1 + px0 * 64 + (wi ^ ((px0 & 7) << 2))] = packh2(v0, v2);
                    smU[OH1 + (px0 + 1) * 64 + (wi ^ (((px0 + 1) & 7) << 2))] =
                        packh2(v1, v3);
                }
            }
        }
        __syncthreads();

        // ---- L2 MMA: 32ch x 64px per warp, K=128 ----
        float acc2[2][8][4];
        {
#pragma unroll
            for (int i = 0; i < 2; i++)
#pragma unroll
                for (int j = 0; j < 8; j++)
#pragma unroll
                    for (int q = 0; q < 4; q++) acc2[i][j][q] = 0.0f;
#pragma unroll
            for (int s = 0; s < 8; s++) {
                uint32_t ds = (uint32_t)(((8 * s) ^ swhi) << 2);
                uint32_t a0[4], a1[4], bb[4][4];
                LDSM4(a0, aW2[0] + ds);
                LDSM4(a1, aW2[1] + ds);
#pragma unroll
                for (int jj = 0; jj < 4; jj++) LDSM4(bb[jj], bH1[jj] + ds);
#pragma unroll
                for (int jj = 0; jj < 4; jj++) {
                    mma16(acc2[0][2 * jj],     a0, bb[jj][0], bb[jj][1]);
                    mma16(acc2[1][2 * jj],     a1, bb[jj][0], bb[jj][1]);
                    mma16(acc2[0][2 * jj + 1], a0, bb[jj][2], bb[jj][3]);
                    mma16(acc2[1][2 * jj + 1], a1, bb[jj][2], bb[jj][3]);
                }
            }
        }
        __syncthreads();   // all h1 reads done before overwrite

        // ---- L2 store: relu -> h region (h2, overwrites h1) ----
        {
#pragma unroll
            for (int i = 0; i < 2; i++) {
                int wi = (cb >> 1) + 8 * i + grp;
#pragma unroll
                for (int j = 0; j < 8; j++) {
                    float v0 = fmaxf(acc2[i][j][0] + b2v[i][0], 0.0f);
                    float v1 = fmaxf(acc2[i][j][1] + b2v[i][0], 0.0f);
                    float v2 = fmaxf(acc2[i][j][2] + b2v[i][1], 0.0f);
                    float v3 = fmaxf(acc2[i][j][3] + b2v[i][1], 0.0f);
                    int px0 = pxb + 8 * j + 2 * t4;
                    smU[OH1 + px0 * 64 + (wi ^ ((px0 & 7) << 2))] = packh2(v0, v2);
                    smU[OH1 + (px0 + 1) * 64 + (wi ^ (((px0 + 1) & 7) << 2))] =
                        packh2(v1, v3);
                }
            }
        }
        __syncthreads();

        // ---- L3 + epilogue + conv(next tile) ----
        {
            float acc[2][4];
#pragma unroll
            for (int j = 0; j < 2; j++)
#pragma unroll
                for (int q = 0; q < 4; q++) acc[j][q] = 0.0f;
#pragma unroll
            for (int s = 0; s < 8; s++) {
                uint32_t ds = (uint32_t)(((8 * s) ^ swhi) << 2);
                uint32_t a[4], bb[4];
                LDSM4(a, aW3 + ds);
                LDSM4(bb, bH2 + ds);
                mma16(acc[0], a, bb[0], bb[1]);
                mma16(acc[1], a, bb[2], bb[3]);
            }
            float* out_noise = dout + (size_t)BATCH * 9 * HW;
            float embv = (grp < CNOISE) ? __ldg(&g_emb[b * 3 + grp]) : 0.0f;
#pragma unroll
            for (int j = 0; j < 2; j++) {
                int px0 = pxb3 + 8 * j + 2 * t4;
                size_t yx = (size_t)y * WW + px0;
                if (grp < CNOISE) {
                    *(float2*)(out_noise + ((size_t)b * 3 + grp) * HW + yx) =
                        make_float2(acc[j][0] + embv, acc[j][1] + embv);
                } else {
                    *(float2*)(dout + ((size_t)b * 9 + (grp - 3)) * HW + yx) =
                        make_float2(acc[j][0], acc[j][1]);
                }
                if (grp < 4) {
                    *(float2*)(dout + ((size_t)b * 9 + (grp + 5)) * HW + yx) =
                        make_float2(acc[j][2], acc[j][3]);
                }
            }

            int nt = tile + gridDim.x;
            if (nt < NTILES)
                conv_tile(xin, hin, sm, smU, nt >> 8, nt & 255,
                          OPH2 + (par ^ 1) * PERCW, cpx, chalf);
        }
        __syncthreads();
        par ^= 1;
    }
}

extern "C" void kernel_launch(void* const* d_in, const int* in_sizes, int n_in,
                              void* d_out, int out_size) {
    const float* x      = (const float*)d_in[0];
    const float* hid    = (const float*)d_in[1];
    const int*   t      = (const int*)d_in[2];
    const float* wp     = (const float*)d_in[3];
    const float* bp     = (const float*)d_in[4];
    const float* w1     = (const float*)d_in[5];
    const float* b1     = (const float*)d_in[6];
    const float* w2     = (const float*)d_in[7];
    const float* b2     = (const float*)d_in[8];
    const float* w3     = (const float*)d_in[9];
    const float* w_time = (const float*)d_in[10];
    const float* b_time = (const float*)d_in[11];
    float* out = (float*)d_out;

    cudaFuncSetAttribute(canet_main,
                         cudaFuncAttributeMaxDynamicSharedMemorySize,
                         SMEM_BYTES);

    int nsm = 148;
    if (cudaDeviceGetAttribute(&nsm, cudaDevAttrMultiProcessorCount, 0)
        != cudaSuccess || nsm <= 0)
        nsm = 148;

    emb_kernel<<<BATCH, TDIM>>>(t, w_time, b_time);
    canet_main<<<nsm, TPB, SMEM_BYTES>>>(
        x, hid, wp, bp, w1, b1, w2, b2, w3, out);
}

// round 9
// speedup vs baseline: 12.0183x; 1.1373x over previous
#include <cuda_runtime.h>
#include <cuda_fp16.h>
#include <cstdint>

#define HH 256
#define WW 256
#define BATCH 16
#define HW 65536
#define CIN 12
#define CNOISE 3
#define PERCC 48
#define HID 128
#define TDIM 256
#define TPB 512
#define TP 256
#define NTILES (BATCH * HW / TP)   // 4096 (tile = one image row)

// SMEM word (b32) offsets
#define OW2   0       // W2 [128 rows][64 words] swizzled, K-permuted fp16-pairs
#define OW1   8192    // W1 [128 rows][32 words] (24 real) swizzled
#define OW3   12288   // W3 [16 rows][64 words] swizzled, K-permuted (rows 12-15 zero)
#define OWPK  13312   // conv weights packed: [12 grp][9 q][4 floats]
#define OBPK  13744   // conv bias packed: [12 grp][4 floats]
#define OB1   13792   // b1 128 fp32
#define OB2   13920   // b2 128 fp32
#define OH1   14048   // h region [256 px][64 words]: h1, then h2 (quad-private rows)
#define OPH2  30432   // perc double buffer: 2 x [256 px][32 words] (quad-private rows)
#define PERCW 8192
#define SMEM_WORDS 46816
#define SMEM_BYTES (SMEM_WORDS * 4)   // 187264

typedef unsigned long long ull;

#define FMA2(d, a, b) \
    asm("fma.rn.f32x2 %0, %1, %2, %0;" : "+l"(d) : "l"(a), "l"(b))
#define PACKF(out, lo, hi) \
    asm("mov.b64 %0, {%1, %2};" : "=l"(out) : "f"(lo), "f"(hi))
#define UNPACKF(lo, hi, in) \
    asm("mov.b64 {%0, %1}, %2;" : "=f"(lo), "=f"(hi) : "l"(in))

// Quad-scoped named barrier: 4 warps / 128 threads, ids 1..4
#define BARQ(id) \
    asm volatile("bar.sync %0, 128;" :: "r"(id) : "memory")

static __device__ __forceinline__ uint32_t packh2(float lo, float hi) {
    __half2 h = __floats2half2_rn(lo, hi);
    return *(uint32_t*)&h;
}

static __device__ __forceinline__ uint32_t smem_u32(const void* p) {
    uint32_t a;
    asm("{ .reg .u64 t; cvta.to.shared.u64 t, %1; cvt.u32.u64 %0, t; }"
        : "=r"(a) : "l"(p));
    return a;
}

static __device__ __forceinline__ void mma16(float d[4], const uint32_t a[4],
                                             uint32_t b0, uint32_t b1) {
    asm volatile(
        "mma.sync.aligned.m16n8k16.row.col.f32.f16.f16.f32 "
        "{%0,%1,%2,%3}, {%4,%5,%6,%7}, {%8,%9}, {%0,%1,%2,%3};"
        : "+f"(d[0]), "+f"(d[1]), "+f"(d[2]), "+f"(d[3])
        : "r"(a[0]), "r"(a[1]), "r"(a[2]), "r"(a[3]), "r"(b0), "r"(b1));
}

#define LDSM4(r, a) \
    asm volatile("ldmatrix.sync.aligned.m8n8.x4.shared.b16 {%0,%1,%2,%3}, [%4];" \
        : "=r"((r)[0]), "=r"((r)[1]), "=r"((r)[2]), "=r"((r)[3]) : "r"(a))

__device__ float g_emb[BATCH * CNOISE];

// ---------------------------------------------------------------------------
__global__ void emb_kernel(const int* __restrict__ t,
                           const float* __restrict__ w_time,
                           const float* __restrict__ b_time) {
    __shared__ float ss[TDIM];
    int b = blockIdx.x, k = threadIdx.x;
    float tb = (float)t[b];
    int f = (k < TDIM / 2) ? k : (k - TDIM / 2);
    const double LN1E4 = 9.210340371976184;
    float invf = (float)exp(-LN1E4 * ((double)(2 * f) / 256.0));
    float ang = tb * invf;
    float pe = (float)((k < TDIM / 2) ? sin((double)ang) : cos((double)ang));
    ss[k] = pe / (1.0f + (float)exp(-(double)pe));
    __syncthreads();
    if (k < CNOISE) {
        float acc = b_time[k];
        for (int q = 0; q < TDIM; q++)
            acc = fmaf(ss[q], w_time[k * TDIM + q], acc);
        g_emb[b * CNOISE + k] = acc;
    }
}

// ---------------------------------------------------------------------------
// Depthwise conv: this thread computes pixel cpx (its quad's range),
// channel half chalf -> perc rows [cpx] of buffer dstW. Packed f32x2 math.
// ---------------------------------------------------------------------------
static __device__ __forceinline__ void conv_tile(
    const float* __restrict__ xin, const float* __restrict__ hin,
    const float* sm, uint32_t* smU, int b, int y, int dstW,
    int cpx, int chalf) {
    float win[6][9];
#pragma unroll
    for (int gi = 0; gi < 6; gi++) {
        int g = chalf * 6 + gi;
        const float* src = (g < CNOISE)
            ? (xin + ((size_t)b * CNOISE + g) * HW)
            : (hin + ((size_t)b * (CIN - CNOISE) + (g - CNOISE)) * HW);
#pragma unroll
        for (int dy = -1; dy <= 1; dy++)
#pragma unroll
            for (int dx = -1; dx <= 1; dx++) {
                int yy = y + dy, xx = cpx + dx;
                float v = 0.0f;
                if (yy >= 0 && yy < HH && xx >= 0 && xx < WW)
                    v = __ldg(src + yy * WW + xx);
                win[gi][(dy + 1) * 3 + (dx + 1)] = v;
            }
    }
    int swz = (cpx & 7) << 2;
#pragma unroll
    for (int gi = 0; gi < 6; gi++) {
        int g = chalf * 6 + gi;
        ulonglong2 bb = *(const ulonglong2*)(sm + OBPK + g * 4);
        ull a01 = bb.x, a23 = bb.y;
#pragma unroll
        for (int q = 0; q < 9; q++) {
            ull wd;
            PACKF(wd, win[gi][q], win[gi][q]);
            ulonglong2 ww = *(const ulonglong2*)(sm + OWPK + (g * 9 + q) * 4);
            FMA2(a01, wd, ww.x);
            FMA2(a23, wd, ww.y);
        }
        float a0, a1, a2, a3;
        UNPACKF(a0, a1, a01);
        UNPACKF(a2, a3, a23);
        *(uint2*)(smU + dstW + cpx * 32 + ((2 * g) ^ swz)) =
            make_uint2(packh2(a0, a1), packh2(a2, a3));
    }
}

// ---------------------------------------------------------------------------
// Persistent pipeline, fp16 m16n8k16, 16 warps in 4 INDEPENDENT quads.
// Quad g (warps 4g..4g+3) owns pixel rows [64g, 64g+64) of every activation
// region; all intra-tile syncs are quad-scoped named barriers, so quads drift
// freely and fill each other's issue bubbles.
// ---------------------------------------------------------------------------
__global__ void __launch_bounds__(TPB, 1)
canet_main(const float* __restrict__ xin, const float* __restrict__ hin,
           const float* __restrict__ wp, const float* __restrict__ bp,
           const float* __restrict__ w1, const float* __restrict__ b1,
           const float* __restrict__ w2, const float* __restrict__ b2,
           const float* __restrict__ w3, float* __restrict__ dout) {
    extern __shared__ float sm[];
    uint32_t* smU = (uint32_t*)sm;
    const int tx = threadIdx.x;

    // ---- one-time staging ----
    for (int i = tx; i < 1024; i += TPB) smU[OW3 + i] = 0u;
    __syncthreads();
    for (int i = tx; i < HID * 64; i += TPB) {       // W2, K-permuted
        int o = i >> 6, kw = i & 63;
        int kc = 16 * (kw >> 3) + (kw & 7);
        smU[OW2 + o * 64 + (kw ^ ((o & 7) << 2))] =
            packh2(w2[o * HID + kc], w2[o * HID + kc + 8]);
    }
    for (int i = tx; i < HID * 24; i += TPB) {       // W1, natural K
        int o = i / 24, kw = i % 24;
        smU[OW1 + o * 32 + (kw ^ ((o & 7) << 2))] =
            packh2(w1[o * PERCC + 2 * kw], w1[o * PERCC + 2 * kw + 1]);
    }
    for (int i = tx; i < CIN * 64; i += TPB) {       // W3, K-permuted
        int o = i >> 6, kw = i & 63;
        int kc = 16 * (kw >> 3) + (kw & 7);
        smU[OW3 + o * 64 + (kw ^ ((o & 7) << 2))] =
            packh2(w3[o * HID + kc], w3[o * HID + kc + 8]);
    }
    for (int i = tx; i < 108; i += TPB) {            // conv weights packed
        int g = i / 9, q = i % 9;
        float4 v = make_float4(wp[(4 * g + 0) * 9 + q], wp[(4 * g + 1) * 9 + q],
                               wp[(4 * g + 2) * 9 + q], wp[(4 * g + 3) * 9 + q]);
        *(float4*)(sm + OWPK + i * 4) = v;
    }
    if (tx < 12)
        *(float4*)(sm + OBPK + tx * 4) =
            make_float4(bp[4 * tx], bp[4 * tx + 1], bp[4 * tx + 2], bp[4 * tx + 3]);
    if (tx < HID) { sm[OB1 + tx] = b1[tx]; sm[OB2 + tx] = b2[tx]; }
    __syncthreads();

    const uint32_t sbase = smem_u32(sm);
    const int w    = tx >> 5, lane = tx & 31;
    const int grp  = lane >> 2, t4 = lane & 3;
    const int quad = w >> 2;             // 0..3, owns px [64*quad, 64*quad+64)
    const int bid  = quad + 1;           // named barrier id
    const int cb   = (w & 3) * 32;       // channel base (32 ch per warp)
    const int pxb  = quad * 64;          // pixel base
    const int pxb3 = w * 16;             // L3 pixel base (within quad range)

    // ---- ldmatrix per-lane invariant addressing ----
    const int swlo = (lane & 1) << 2;
    const int swhi = (lane & 6) << 2;
    const int cA   = ((lane >> 4) << 2) ^ swlo;
    const int cB   = (((lane >> 3) & 1) << 2) ^ swlo;
    const int lr   = lane & 15;
    const int bRow = (lane & 7) + ((lane >> 4) << 3);

    uint32_t aW1[2], aW2[2], bP0[4], bH1[4];
#pragma unroll
    for (int i = 0; i < 2; i++) {
        aW1[i] = sbase + 4 * (OW1 + (cb + 16 * i + lr) * 32 + cA);
        aW2[i] = sbase + 4 * (OW2 + (cb + 16 * i + lr) * 64 + cA);
    }
#pragma unroll
    for (int j = 0; j < 4; j++) {
        bP0[j] = sbase + 4 * (OPH2 + (pxb + 16 * j + bRow) * 32 + cB);
        bH1[j] = sbase + 4 * (OH1 + (pxb + 16 * j + bRow) * 64 + cB);
    }
    const uint32_t aW3 = sbase + 4 * (OW3 + lr * 64 + cA);
    const uint32_t bH2 = sbase + 4 * (OH1 + (pxb3 + bRow) * 64 + cB);

    float b1v[2][2], b2v[2][2];
#pragma unroll
    for (int i = 0; i < 2; i++) {
        b1v[i][0] = sm[OB1 + cb + 16 * i + grp];
        b1v[i][1] = sm[OB1 + cb + 16 * i + 8 + grp];
        b2v[i][0] = sm[OB2 + cb + 16 * i + grp];
        b2v[i][1] = sm[OB2 + cb + 16 * i + 8 + grp];
    }

    // conv mapping: quad-local. 128 threads cover 64 px x 2 channel-halves.
    const int tq    = tx & 127;              // thread-in-quad
    const int cpx   = pxb + (tq & 63);       // this thread's pixel
    const int chalf = tq >> 6;               // channel half (groups 6h..6h+5)

    // ---- prologue: conv for first tile into buffer 0 (quad's rows) ----
    {
        int t0 = blockIdx.x;
        conv_tile(xin, hin, sm, smU, t0 >> 8, t0 & 255, OPH2, cpx, chalf);
    }
    BARQ(bid);
    int par = 0;

    for (int tile = blockIdx.x; tile < NTILES; tile += gridDim.x) {
        const int b = tile >> 8;
        const int y = tile & 255;
        const uint32_t pofs = (uint32_t)par << 15;   // 8192 words = 32768 B

        // ---- L1: 32ch x 64px per warp, K=48; relu-store -> h region ----
        {
            float acc[2][8][4];
#pragma unroll
            for (int i = 0; i < 2; i++)
#pragma unroll
                for (int j = 0; j < 8; j++)
#pragma unroll
                    for (int q = 0; q < 4; q++) acc[i][j][q] = 0.0f;
#pragma unroll
            for (int s = 0; s < 3; s++) {
                uint32_t ds = (uint32_t)(((8 * s) ^ swhi) << 2);
                uint32_t a0[4], a1[4], bb[4][4];
                LDSM4(a0, aW1[0] + ds);
                LDSM4(a1, aW1[1] + ds);
#pragma unroll
                for (int jj = 0; jj < 4; jj++) LDSM4(bb[jj], bP0[jj] + pofs + ds);
#pragma unroll
                for (int jj = 0; jj < 4; jj++) {
                    mma16(acc[0][2 * jj],     a0, bb[jj][0], bb[jj][1]);
                    mma16(acc[1][2 * jj],     a1, bb[jj][0], bb[jj][1]);
                    mma16(acc[0][2 * jj + 1], a0, bb[jj][2], bb[jj][3]);
                    mma16(acc[1][2 * jj + 1], a1, bb[jj][2], bb[jj][3]);
                }
            }
#pragma unroll
            for (int i = 0; i < 2; i++) {
                int wi = (cb >> 1) + 8 * i + grp;
#pragma unroll
                for (int j = 0; j < 8; j++) {
                    float v0 = fmaxf(acc[i][j][0] + b1v[i][0], 0.0f);
                    float v1 = fmaxf(acc[i][j][1] + b1v[i][0], 0.0f);
                    float v2 = fmaxf(acc[i][j][2] + b1v[i][1], 0.0f);
                    float v3 = fmaxf(acc[i][j][3] + b1v[i][1], 0.0f);
                    int px0 = pxb + 8 * j + 2 * t4;
                    smU[OH1 + px0 * 64 + (wi ^ ((px0 & 7) << 2))] = packh2(v0, v2);
                    smU[OH1 + (px0 + 1) * 64 + (wi ^ (((px0 + 1) & 7) << 2))] =
                        packh2(v1, v3);
                }
            }
        }
        BARQ(bid);

        // ---- L2 MMA: 32ch x 64px per warp, K=128 ----
        float acc2[2][8][4];
        {
#pragma unroll
            for (int i = 0; i < 2; i++)
#pragma unroll
                for (int j = 0; j < 8; j++)
#pragma unroll
                    for (int q = 0; q < 4; q++) acc2[i][j][q] = 0.0f;
#pragma unroll
            for (int s = 0; s < 8; s++) {
                uint32_t ds = (uint32_t)(((8 * s) ^ swhi) << 2);
                uint32_t a0[4], a1[4], bb[4][4];
                LDSM4(a0, aW2[0] + ds);
                LDSM4(a1, aW2[1] + ds);
#pragma unroll
                for (int jj = 0; jj < 4; jj++) LDSM4(bb[jj], bH1[jj] + ds);
#pragma unroll
                for (int jj = 0; jj < 4; jj++) {
                    mma16(acc2[0][2 * jj],     a0, bb[jj][0], bb[jj][1]);
                    mma16(acc2[1][2 * jj],     a1, bb[jj][0], bb[jj][1]);
                    mma16(acc2[0][2 * jj + 1], a0, bb[jj][2], bb[jj][3]);
                    mma16(acc2[1][2 * jj + 1], a1, bb[jj][2], bb[jj][3]);
                }
            }
        }
        BARQ(bid);   // quad's h1 reads done before overwrite

        // ---- L2 store: relu -> h region (h2, overwrites h1 rows) ----
        {
#pragma unroll
            for (int i = 0; i < 2; i++) {
                int wi = (cb >> 1) + 8 * i + grp;
#pragma unroll
                for (int j = 0; j < 8; j++) {
                    float v0 = fmaxf(acc2[i][j][0] + b2v[i][0], 0.0f);
                    float v1 = fmaxf(acc2[i][j][1] + b2v[i][0], 0.0f);
                    float v2 = fmaxf(acc2[i][j][2] + b2v[i][1], 0.0f);
                    float v3 = fmaxf(acc2[i][j][3] + b2v[i][1], 0.0f);
                    int px0 = pxb + 8 * j + 2 * t4;
                    smU[OH1 + px0 * 64 + (wi ^ ((px0 & 7) << 2))] = packh2(v0, v2);
                    smU[OH1 + (px0 + 1) * 64 + (wi ^ (((px0 + 1) & 7) << 2))] =
                        packh2(v1, v3);
                }
            }
        }
        BARQ(bid);

        // ---- L3 + epilogue + conv(next tile, quad's rows) ----
        {
            float acc[2][4];
#pragma unroll
            for (int j = 0; j < 2; j++)
#pragma unroll
                for (int q = 0; q < 4; q++) acc[j][q] = 0.0f;
#pragma unroll
            for (int s = 0; s < 8; s++) {
                uint32_t ds = (uint32_t)(((8 * s) ^ swhi) << 2);
                uint32_t a[4], bb[4];
                LDSM4(a, aW3 + ds);
                LDSM4(bb, bH2 + ds);
                mma16(acc[0], a, bb[0], bb[1]);
                mma16(acc[1], a, bb[2], bb[3]);
            }
            float* out_noise = dout + (size_t)BATCH * 9 * HW;
            float embv = (grp < CNOISE) ? __ldg(&g_emb[b * 3 + grp]) : 0.0f;
#pragma unroll
            for (int j = 0; j < 2; j++) {
                int px0 = pxb3 + 8 * j + 2 * t4;
                size_t yx = (size_t)y * WW + px0;
                if (grp < CNOISE) {
                    *(float2*)(out_noise + ((size_t)b * 3 + grp) * HW + yx) =
                        make_float2(acc[j][0] + embv, acc[j][1] + embv);
                } else {
                    *(float2*)(dout + ((size_t)b * 9 + (grp - 3)) * HW + yx) =
                        make_float2(acc[j][0], acc[j][1]);
                }
                if (grp < 4) {
                    *(float2*)(dout + ((size_t)b * 9 + (grp + 5)) * HW + yx) =
                        make_float2(acc[j][2], acc[j][3]);
                }
            }

            int nt = tile + gridDim.x;
            if (nt < NTILES)
                conv_tile(xin, hin, sm, smU, nt >> 8, nt & 255,
                          OPH2 + (par ^ 1) * PERCW, cpx, chalf);
        }
        BARQ(bid);
        par ^= 1;
    }
}

extern "C" void kernel_launch(void* const* d_in, const int* in_sizes, int n_in,
                              void* d_out, int out_size) {
    const float* x      = (const float*)d_in[0];
    const float* hid    = (const float*)d_in[1];
    const int*   t      = (const int*)d_in[2];
    const float* wp     = (const float*)d_in[3];
    const float* bp     = (const float*)d_in[4];
    const float* w1     = (const float*)d_in[5];
    const float* b1     = (const float*)d_in[6];
    const float* w2     = (const float*)d_in[7];
    const float* b2     = (const float*)d_in[8];
    const float* w3     = (const float*)d_in[9];
    const float* w_time = (const float*)d_in[10];
    const float* b_time = (const float*)d_in[11];
    float* out = (float*)d_out;

    cudaFuncSetAttribute(canet_main,
                         cudaFuncAttributeMaxDynamicSharedMemorySize,
                         SMEM_BYTES);

    int nsm = 148;
    if (cudaDeviceGetAttribute(&nsm, cudaDevAttrMultiProcessorCount, 0)
        != cudaSuccess || nsm <= 0)
        nsm = 148;

    emb_kernel<<<BATCH, TDIM>>>(t, w_time, b_time);
    canet_main<<<nsm, TPB, SMEM_BYTES>>>(
        x, hid, wp, bp, w1, b1, w2, b2, w3, out);
}